// round 4
// baseline (speedup 1.0000x reference)
#include <cuda_runtime.h>
#include <cstdint>

#define FULL 0xFFFFFFFFu

constexpr int Bb = 512;
constexpr float ALPHA = 0.2f;

__device__ float g_u1[2][128];
__device__ float g_u2[2][128];
__device__ float g_u3[2][128];
__device__ float g_c1[2];

__global__ void precompute_kernel(
    const float* __restrict__ w2a, const float* __restrict__ w3a,
    const float* __restrict__ qa,  const float* __restrict__ aa,
    const float* __restrict__ a2a,
    const float* __restrict__ w2b, const float* __restrict__ w3b,
    const float* __restrict__ qb,  const float* __restrict__ ab,
    const float* __restrict__ a2b)
{
    int layer = threadIdx.x >> 7;
    int k = threadIdx.x & 127;
    const float* w2 = layer ? w2b : w2a;
    const float* w3 = layer ? w3b : w3a;
    const float* q  = layer ? qb  : qa;
    const float* a  = layer ? ab  : aa;
    const float* a2 = layer ? a2b : a2a;
    float u1 = 0.f, u2 = 0.f, u3 = 0.f;
    #pragma unroll 4
    for (int c = 0; c < 128; c++) {
        float w2v = w2[k * 128 + c];
        u1 += w2v * a[128 + c];
        u2 += w2v * a2[c];
        u3 += w3[k * 128 + c] * a2[128 + c];
    }
    g_u1[layer][k] = u1;
    g_u2[layer][k] = u2;
    g_u3[layer][k] = u3;
    __shared__ float red[256];
    red[threadIdx.x] = q[k] * a[k];
    __syncthreads();
    if (k == 0) {
        float s = 0.f;
        for (int i = 0; i < 128; i++) s += red[layer * 128 + i];
        g_c1[layer] = s;
    }
}

// smem (floats): x 8192 | resid 8192 | xtb 8192 | edge 16384 | e1v 64 | s2 64
// | f2 128 | wtc 32*128=4096 | emask 256 | nmask 256
// | elist16 128*48 u16 = 3072 | nlist16 64*64 u16 = 2048 | idlist16 128 u16 = 64
// | ecnt 128 | ncnt 64
constexpr int SMEM_FLOATS = 8192 * 3 + 16384 + 64 + 64 + 128 + 4096 + 256 + 256
                          + 3072 + 2048 + 64 + 128 + 64;
constexpr int SMEM_BYTES = SMEM_FLOATS * 4;  // 204800 B

__global__ __launch_bounds__(1024, 1) void session_kernel(
    const int*   __restrict__ inputs,
    const float* __restrict__ HT,
    const float* __restrict__ emb,
    const float* __restrict__ emb2,
    const float* __restrict__ g2w,
    float*       __restrict__ out)
{
    extern __shared__ float smem[];
    float* x     = smem;
    float* resid = x + 8192;
    float* xtb   = resid + 8192;
    float* edge  = xtb + 8192;
    float* e1v   = edge + 16384;
    float* s2    = e1v + 64;
    float* f2    = s2 + 64;
    float* wtc   = f2 + 128;
    unsigned long long* emask = (unsigned long long*)(wtc + 4096);
    unsigned long long* nmask = emask + 128;
    uint16_t* elist  = (uint16_t*)(nmask + 128);     // 128*48 entries, val = j*32
    uint16_t* nlist  = elist + 128 * 48;             // 64*64 entries,  val = e*32
    uint16_t* idlist = nlist + 64 * 64;              // 128 entries,    val = i*32
    int* ecnt = (int*)(idlist + 128);
    int* ncnt = ecnt + 128;

    const int tid  = threadIdx.x;
    const int warp = tid >> 5;
    const int lane = tid & 31;
    const int b    = blockIdx.x;
    const size_t BLD = (size_t)Bb * 64 * 128;

    // ---- Phase 0: gathers + masks + pre-scaled index lists ----
    for (int j = warp; j < 64; j += 32) {
        int tok = inputs[b * 64 + j];
        float4 v = ((const float4*)(emb + (size_t)tok * 128))[lane];
        ((float4*)(x + j * 128))[lane] = v;
        ((float4*)(resid + j * 128))[lane] = v;
        float4 v2 = ((const float4*)(emb2 + (size_t)tok * 128))[lane];
        ((float4*)(out + 2 * BLD + ((size_t)b * 64 + j) * 128))[lane] = v2;
    }
    for (int e = warp; e < 128; e += 32) {
        const float* row = HT + ((size_t)b * 128 + e) * 64;
        unsigned lo = __ballot_sync(FULL, row[lane] > 0.f);
        unsigned hi = __ballot_sync(FULL, row[lane + 32] > 0.f);
        if (lane == 0)
            emask[e] = (unsigned long long)lo | ((unsigned long long)hi << 32);
    }
    if (tid < 128) idlist[tid] = (uint16_t)(tid * 32);
    __syncthreads();
    if (tid < 64) {
        unsigned long long m0 = 0, m1 = 0;
        #pragma unroll 4
        for (int e = 0; e < 64; e++) {
            m0 |= ((emask[e] >> tid) & 1ull) << e;
            m1 |= ((emask[e + 64] >> tid) & 1ull) << e;
        }
        nmask[2 * tid] = m0;
        nmask[2 * tid + 1] = m1;
    } else if (tid < 192) {
        int e = tid - 64;
        unsigned long long m = emask[e];
        int c = 0;
        uint16_t* l = elist + e * 48;
        while (m) { int j = __ffsll(m) - 1; m &= m - 1; l[c++] = (uint16_t)(j * 32); }
        ecnt[e] = c;
    }
    __syncthreads();
    if (tid < 64) {
        unsigned long long m0 = nmask[2 * tid], m1 = nmask[2 * tid + 1];
        int c = 0;
        uint16_t* l = nlist + tid * 64;
        while (m0) { int e = __ffsll(m0) - 1; m0 &= m0 - 1; l[c++] = (uint16_t)(e * 32); }
        while (m1) { int e = __ffsll(m1) - 1; m1 &= m1 - 1; l[c++] = (uint16_t)((e + 64) * 32); }
        ncnt[tid] = c;
    }
    __syncthreads();

    float* w = wtc + warp * 128;

    for (int layer = 0; layer < 2; layer++) {
        const float* xt = x;
        // ---- Step A (layer 1 only): xtb = x @ g2_w, 2 rows per warp ----
        if (layer == 1) {
            float4 acc0 = make_float4(0.f, 0.f, 0.f, 0.f);
            float4 acc1 = make_float4(0.f, 0.f, 0.f, 0.f);
            const float4* w4 = (const float4*)g2w;
            for (int k4 = 0; k4 < 32; k4++) {
                float4 xv0 = ((const float4*)(x + warp * 128))[k4];
                float4 xv1 = ((const float4*)(x + (warp + 32) * 128))[k4];
                #pragma unroll
                for (int kk = 0; kk < 4; kk++) {
                    float4 wr = w4[(k4 * 4 + kk) * 32 + lane];
                    float s0 = ((const float*)&xv0)[kk];
                    float s1 = ((const float*)&xv1)[kk];
                    acc0.x += s0 * wr.x; acc0.y += s0 * wr.y;
                    acc0.z += s0 * wr.z; acc0.w += s0 * wr.w;
                    acc1.x += s1 * wr.x; acc1.y += s1 * wr.y;
                    acc1.z += s1 * wr.z; acc1.w += s1 * wr.w;
                }
            }
            ((float4*)(xtb + warp * 128))[lane] = acc0;
            ((float4*)(xtb + (warp + 32) * 128))[lane] = acc1;
            xt = xtb;
            __syncthreads();
        }

        // ---- Step B: e1[j], s2[j] ----
        const float  c1   = g_c1[layer];
        const float4* u1v4 = (const float4*)g_u1[layer];
        const float4* u2v4 = (const float4*)g_u2[layer];
        const float4* u3v4 = (const float4*)g_u3[layer];
        for (int j = warp; j < 64; j += 32) {
            float4 xv = ((const float4*)(x + j * 128))[lane];
            float4 u1v = u1v4[lane], u2v = u2v4[lane];
            float p1 = xv.x * u1v.x + xv.y * u1v.y + xv.z * u1v.z + xv.w * u1v.w;
            float p2 = xv.x * u2v.x + xv.y * u2v.y + xv.z * u2v.z + xv.w * u2v.w;
            #pragma unroll
            for (int off = 16; off; off >>= 1) {
                p1 += __shfl_xor_sync(FULL, p1, off);
                p2 += __shfl_xor_sync(FULL, p2, off);
            }
            if (lane == 0) {
                float e = c1 + p1;
                e1v[j] = e > 0.f ? e : ALPHA * e;
                s2[j] = p2;
            }
        }
        __syncthreads();

        // ---- Step C: edge softmax + edge = att @ xt + f2 ----
        const float4* xt4 = (const float4*)xt;
        for (int e = warp; e < 128; e += 32) {
            unsigned long long m = emask[e];
            int cnt;
            const uint16_t* list;
            __syncwarp();
            if (m == 0ull) {
                w[lane] = 1.f / 64.f;
                w[lane + 32] = 1.f / 64.f;
                list = idlist; cnt = 64;
            } else {
                cnt = ecnt[e]; list = elist + e * 48;
                bool b0 = (m >> lane) & 1ull, b1 = (m >> (lane + 32)) & 1ull;
                float v0 = b0 ? e1v[lane] : -1e30f;
                float v1 = b1 ? e1v[lane + 32] : -1e30f;
                float mx = fmaxf(v0, v1);
                #pragma unroll
                for (int off = 16; off; off >>= 1)
                    mx = fmaxf(mx, __shfl_xor_sync(FULL, mx, off));
                float w0 = b0 ? __expf(v0 - mx) : 0.f;
                float w1 = b1 ? __expf(v1 - mx) : 0.f;
                float s = w0 + w1;
                #pragma unroll
                for (int off = 16; off; off >>= 1)
                    s += __shfl_xor_sync(FULL, s, off);
                float inv = 1.f / s;
                if (b0) w[__popcll(m & ((1ull << lane) - 1))] = w0 * inv;
                if (b1) w[__popcll(m & ((1ull << (lane + 32)) - 1))] = w1 * inv;
            }
            __syncwarp();
            float4 a0 = make_float4(0.f, 0.f, 0.f, 0.f);
            float4 a1 = make_float4(0.f, 0.f, 0.f, 0.f);
            int i = 0;
            for (; i + 4 <= cnt; i += 4) {
                ushort4 j4 = *(const ushort4*)(list + i);
                float4 wv = *(const float4*)(w + i);
                float4 v0 = xt4[j4.x + lane];
                float4 v1 = xt4[j4.y + lane];
                float4 v2 = xt4[j4.z + lane];
                float4 v3 = xt4[j4.w + lane];
                a0.x += wv.x * v0.x; a0.y += wv.x * v0.y; a0.z += wv.x * v0.z; a0.w += wv.x * v0.w;
                a1.x += wv.y * v1.x; a1.y += wv.y * v1.y; a1.z += wv.y * v1.z; a1.w += wv.y * v1.w;
                a0.x += wv.z * v2.x; a0.y += wv.z * v2.y; a0.z += wv.z * v2.z; a0.w += wv.z * v2.w;
                a1.x += wv.w * v3.x; a1.y += wv.w * v3.y; a1.z += wv.w * v3.z; a1.w += wv.w * v3.w;
            }
            for (; i < cnt; i++) {
                int jo = list[i];
                float wj = w[i];
                float4 v = xt4[jo + lane];
                a0.x += wj * v.x; a0.y += wj * v.y; a0.z += wj * v.z; a0.w += wj * v.w;
            }
            float4 acc = make_float4(a0.x + a1.x, a0.y + a1.y, a0.z + a1.z, a0.w + a1.w);
            ((float4*)edge)[e * 32 + lane] = acc;
            float4 u3v = u3v4[lane];
            float p = acc.x * u3v.x + acc.y * u3v.y + acc.z * u3v.z + acc.w * u3v.w;
            #pragma unroll
            for (int off = 16; off; off >>= 1)
                p += __shfl_xor_sync(FULL, p, off);
            if (lane == 0) f2[e] = p;
        }
        __syncthreads();

        // ---- Step D: node softmax + node = att @ edge + resid ----
        const float4* edge4 = (const float4*)edge;
        for (int j = warp; j < 64; j += 32) {
            unsigned long long m0 = nmask[2 * j], m1 = nmask[2 * j + 1];
            float ss = s2[j];
            int cnt;
            const uint16_t* list;
            __syncwarp();
            if ((m0 | m1) == 0ull) {
                w[lane] = w[lane + 32] = w[lane + 64] = w[lane + 96] = 1.f / 128.f;
                list = idlist; cnt = 128;
            } else {
                cnt = ncnt[j]; list = nlist + j * 64;
                bool b0 = (m0 >> lane) & 1ull, b1 = (m0 >> (lane + 32)) & 1ull;
                bool b2 = (m1 >> lane) & 1ull, b3 = (m1 >> (lane + 32)) & 1ull;
                float t0 = ss + f2[lane];       t0 = t0 > 0.f ? t0 : ALPHA * t0;
                float t1 = ss + f2[lane + 32];  t1 = t1 > 0.f ? t1 : ALPHA * t1;
                float t2 = ss + f2[lane + 64];  t2 = t2 > 0.f ? t2 : ALPHA * t2;
                float t3 = ss + f2[lane + 96];  t3 = t3 > 0.f ? t3 : ALPHA * t3;
                float v0 = b0 ? t0 : -1e30f;
                float v1 = b1 ? t1 : -1e30f;
                float v2 = b2 ? t2 : -1e30f;
                float v3 = b3 ? t3 : -1e30f;
                float mx = fmaxf(fmaxf(v0, v1), fmaxf(v2, v3));
                #pragma unroll
                for (int off = 16; off; off >>= 1)
                    mx = fmaxf(mx, __shfl_xor_sync(FULL, mx, off));
                float w0 = b0 ? __expf(v0 - mx) : 0.f;
                float w1 = b1 ? __expf(v1 - mx) : 0.f;
                float w2 = b2 ? __expf(v2 - mx) : 0.f;
                float w3 = b3 ? __expf(v3 - mx) : 0.f;
                float s = w0 + w1 + w2 + w3;
                #pragma unroll
                for (int off = 16; off; off >>= 1)
                    s += __shfl_xor_sync(FULL, s, off);
                float inv = 1.f / s;
                int base1 = __popcll(m0);
                if (b0) w[__popcll(m0 & ((1ull << lane) - 1))] = w0 * inv;
                if (b1) w[__popcll(m0 & ((1ull << (lane + 32)) - 1))] = w1 * inv;
                if (b2) w[base1 + __popcll(m1 & ((1ull << lane) - 1))] = w2 * inv;
                if (b3) w[base1 + __popcll(m1 & ((1ull << (lane + 32)) - 1))] = w3 * inv;
            }
            __syncwarp();
            float4 a0 = make_float4(0.f, 0.f, 0.f, 0.f);
            float4 a1 = make_float4(0.f, 0.f, 0.f, 0.f);
            int i = 0;
            for (; i + 4 <= cnt; i += 4) {
                ushort4 e4 = *(const ushort4*)(list + i);
                float4 wv = *(const float4*)(w + i);
                float4 v0 = edge4[e4.x + lane];
                float4 v1 = edge4[e4.y + lane];
                float4 v2 = edge4[e4.z + lane];
                float4 v3 = edge4[e4.w + lane];
                a0.x += wv.x * v0.x; a0.y += wv.x * v0.y; a0.z += wv.x * v0.z; a0.w += wv.x * v0.w;
                a1.x += wv.y * v1.x; a1.y += wv.y * v1.y; a1.z += wv.y * v1.z; a1.w += wv.y * v1.w;
                a0.x += wv.z * v2.x; a0.y += wv.z * v2.y; a0.z += wv.z * v2.z; a0.w += wv.z * v2.w;
                a1.x += wv.w * v3.x; a1.y += wv.w * v3.y; a1.z += wv.w * v3.z; a1.w += wv.w * v3.w;
            }
            for (; i < cnt; i++) {
                int eo = list[i];
                float we = w[i];
                float4 v = edge4[eo + lane];
                a0.x += we * v.x; a0.y += we * v.y; a0.z += we * v.z; a0.w += we * v.w;
            }
            float4 rv = ((const float4*)(resid + j * 128))[lane];
            float4 acc = make_float4(a0.x + a1.x + rv.x, a0.y + a1.y + rv.y,
                                     a0.z + a1.z + rv.z, a0.w + a1.w + rv.w);
            ((float4*)(x + j * 128))[lane] = acc;
        }
        __syncthreads();
    }

    // ---- Output: (x, x, nodes2) ----
    for (int j = warp; j < 64; j += 32) {
        float4 v = ((const float4*)(x + j * 128))[lane];
        ((float4*)(out + ((size_t)b * 64 + j) * 128))[lane] = v;
        ((float4*)(out + BLD + ((size_t)b * 64 + j) * 128))[lane] = v;
    }
}

extern "C" void kernel_launch(void* const* d_in, const int* in_sizes, int n_in,
                              void* d_out, int out_size)
{
    const int*   inputs = (const int*)d_in[0];
    const float* HT     = (const float*)d_in[1];
    const float* emb    = (const float*)d_in[4];
    const float* emb2   = (const float*)d_in[5];
    const float* g1_w2  = (const float*)d_in[6];
    const float* g1_w3  = (const float*)d_in[7];
    const float* g1_q   = (const float*)d_in[8];
    const float* g1_a   = (const float*)d_in[9];
    const float* g1_a2  = (const float*)d_in[10];
    const float* g2_w   = (const float*)d_in[11];
    const float* g2_w2  = (const float*)d_in[12];
    const float* g2_w3  = (const float*)d_in[13];
    const float* g2_q   = (const float*)d_in[14];
    const float* g2_a   = (const float*)d_in[15];
    const float* g2_a2  = (const float*)d_in[16];
    float* out = (float*)d_out;

    cudaFuncSetAttribute(session_kernel,
                         cudaFuncAttributeMaxDynamicSharedMemorySize, SMEM_BYTES);

    precompute_kernel<<<1, 256>>>(g1_w2, g1_w3, g1_q, g1_a, g1_a2,
                                  g2_w2, g2_w3, g2_q, g2_a, g2_a2);
    session_kernel<<<Bb, 1024, SMEM_BYTES>>>(inputs, HT, emb, emb2, g2_w, out);
}

// round 6
// speedup vs baseline: 1.4838x; 1.4838x over previous
#include <cuda_runtime.h>
#include <cuda_bf16.h>
#include <cstdint>

#define FULL 0xFFFFFFFFu
constexpr int Bb = 512;
constexpr float ALPHA = 0.2f;

// ---------------- mma / ldmatrix helpers (baseline PTX, sm_80+) ----------------
__device__ __forceinline__ void mma16816(float* d, const uint32_t* a, const uint32_t* b) {
    asm volatile("mma.sync.aligned.m16n8k16.row.col.f32.bf16.bf16.f32 "
        "{%0,%1,%2,%3}, {%4,%5,%6,%7}, {%8,%9}, {%0,%1,%2,%3};"
        : "+f"(d[0]), "+f"(d[1]), "+f"(d[2]), "+f"(d[3])
        : "r"(a[0]), "r"(a[1]), "r"(a[2]), "r"(a[3]), "r"(b[0]), "r"(b[1]));
}
__device__ __forceinline__ void ldm_x4(uint32_t* r, uint32_t addr) {
    asm volatile("ldmatrix.sync.aligned.m8n8.x4.shared.b16 {%0,%1,%2,%3}, [%4];"
        : "=r"(r[0]), "=r"(r[1]), "=r"(r[2]), "=r"(r[3]) : "r"(addr));
}
__device__ __forceinline__ void ldm_x4t(uint32_t* r, uint32_t addr) {
    asm volatile("ldmatrix.sync.aligned.m8n8.x4.trans.shared.b16 {%0,%1,%2,%3}, [%4];"
        : "=r"(r[0]), "=r"(r[1]), "=r"(r[2]), "=r"(r[3]) : "r"(addr));
}
__device__ __forceinline__ void ldm_x2t(uint32_t* r, uint32_t addr) {
    asm volatile("ldmatrix.sync.aligned.m8n8.x2.trans.shared.b16 {%0,%1}, [%2];"
        : "=r"(r[0]), "=r"(r[1]) : "r"(addr));
}
__device__ __forceinline__ uint32_t smem_u32(const void* p) {
    uint32_t a;
    asm("{ .reg .u64 t; cvta.to.shared.u64 t, %1; cvt.u32.u64 %0, t; }" : "=r"(a) : "l"(p));
    return a;
}

// ---------------- precomputed globals ----------------
// g_u: 0=u1a 1=u2a 2=u3a 3=u1b 4=u2b 5=u3g(=g2w@u3b)
__device__ float g_u[6][128];
__device__ float g_c1[2];
// g2w as bf16 hi[128][136] | lo[128][136] (row=k, col=d), 69632 bytes
__device__ __align__(16) uint8_t g_w2img[69632];

__global__ void precompute_kernel(
    const float* __restrict__ w2a, const float* __restrict__ w3a,
    const float* __restrict__ qa,  const float* __restrict__ aa,
    const float* __restrict__ a2a,
    const float* __restrict__ w2b, const float* __restrict__ w3b,
    const float* __restrict__ qb,  const float* __restrict__ ab,
    const float* __restrict__ a2b,
    const float* __restrict__ g2w)
{
    int layer = threadIdx.x >> 7;
    int k = threadIdx.x & 127;
    const float* w2 = layer ? w2b : w2a;
    const float* w3 = layer ? w3b : w3a;
    const float* q  = layer ? qb  : qa;
    const float* a  = layer ? ab  : aa;
    const float* a2 = layer ? a2b : a2a;
    float u1 = 0.f, u2 = 0.f, u3 = 0.f;
    #pragma unroll 4
    for (int c = 0; c < 128; c++) {
        float w2v = w2[k * 128 + c];
        u1 += w2v * a[128 + c];
        u2 += w2v * a2[c];
        u3 += w3[k * 128 + c] * a2[128 + c];
    }
    __shared__ float u3sh[128];
    __shared__ float red[256];
    if (layer == 0) { g_u[0][k] = u1; g_u[1][k] = u2; g_u[2][k] = u3; }
    else            { g_u[3][k] = u1; g_u[4][k] = u2; u3sh[k] = u3; }
    red[threadIdx.x] = q[k] * a[k];
    __syncthreads();
    if (k == 0) {
        float s = 0.f;
        for (int i = 0; i < 128; i++) s += red[layer * 128 + i];
        g_c1[layer] = s;
    }
    if (layer == 0) {  // u3g = g2w @ u3b
        float s = 0.f;
        #pragma unroll 4
        for (int n = 0; n < 128; n++) s += g2w[k * 128 + n] * u3sh[n];
        g_u[5][k] = s;
    }
}

__global__ void img_kernel(const float* __restrict__ g2w) {
    int idx = blockIdx.x * 256 + threadIdx.x;  // 64 x 256 = 16384
    int kk = idx >> 7, d = idx & 127;
    float v = g2w[kk * 128 + d];
    __nv_bfloat16 h = __float2bfloat16(v);
    *(__nv_bfloat16*)(g_w2img + (kk * 136 + d) * 2) = h;
    *(__nv_bfloat16*)(g_w2img + 34816 + (kk * 136 + d) * 2) =
        __float2bfloat16(v - __bfloat162float(h));
}

// ---------------- smem layout (bytes) ----------------
// strides in bf16: 72 for 64-wide (144B rows), 136 for 128-wide (272B rows)
constexpr int SM_ATT1  = 0;        // hi [128][72] 18432 | lo +18432 ; total 36864
constexpr int SM_ATTN  = 36864;    // hi [64][136] 17408 | lo +17408 ; total 34816
constexpr int SM_G2W   = 0;        // 69632 (overlaps ATT1+ATTN; layer1 only, after P1)
constexpr int SM_X     = 71680;    // hi [64][136] | lo ; 34816
constexpr int SM_Y     = 106496;   // hi [64][136] | lo ; 34816
constexpr int SM_P     = 141312;   // hi [64][72] 9216 | lo ; 18432
constexpr int SM_RESID = 159744;   // fp32 [64][128] 32768
constexpr int SM_E1V   = 192512;
constexpr int SM_S2    = 192768;
constexpr int SM_VV    = 193024;
constexpr int SM_DXA   = 193280;
constexpr int SM_DXB   = 193536;
constexpr int SM_DXC   = 193792;
constexpr int SM_F2    = 194048;   // 128 f
constexpr int SM_DEA   = 194560;
constexpr int SM_DEB   = 195072;
constexpr int SM_DEC   = 195584;
constexpr int SM_EMASK = 196096;   // 128 u64
constexpr int SM_NMASK = 197120;   // 64 x 2 u64
constexpr int SMEM_BYTES = 198144;

#define RADD(v) { _Pragma("unroll") for (int _o = 16; _o; _o >>= 1) v += __shfl_xor_sync(FULL, v, _o); }
#define RMAX(v) { _Pragma("unroll") for (int _o = 16; _o; _o >>= 1) v = fmaxf(v, __shfl_xor_sync(FULL, v, _o)); }

// store fp32 pair as bf16 hi/lo pair at byte offset (4B-aligned)
__device__ __forceinline__ void st2(uint8_t* sm, int off, int loB, float a, float b) {
    __nv_bfloat16 h0 = __float2bfloat16(a), h1 = __float2bfloat16(b);
    *(__nv_bfloat162*)(sm + off) = __halves2bfloat162(h0, h1);
    *(__nv_bfloat162*)(sm + off + loB) = __floats2bfloat162_rn(
        a - __bfloat162float(h0), b - __bfloat162float(h1));
}
__device__ __forceinline__ void st1(uint8_t* sm, int off, int loB, float a) {
    __nv_bfloat16 h = __float2bfloat16(a);
    *(__nv_bfloat16*)(sm + off) = h;
    *(__nv_bfloat16*)(sm + off + loB) = __float2bfloat16(a - __bfloat162float(h));
}

__global__ __launch_bounds__(1024, 1) void session_kernel(
    const int*   __restrict__ inputs,
    const float* __restrict__ HT,
    const float* __restrict__ emb,
    const float* __restrict__ emb2,
    float*       __restrict__ out)
{
    extern __shared__ __align__(16) uint8_t sm[];
    const int tid  = threadIdx.x;
    const int warp = tid >> 5;
    const int lane = tid & 31;
    const int b    = blockIdx.x;
    const size_t BLD = (size_t)Bb * 64 * 128;
    uint32_t sbase = smem_u32(sm);

    float* e1v = (float*)(sm + SM_E1V);
    float* s2v = (float*)(sm + SM_S2);
    float* vv  = (float*)(sm + SM_VV);
    float* dxa = (float*)(sm + SM_DXA);
    float* dxb = (float*)(sm + SM_DXB);
    float* dxc = (float*)(sm + SM_DXC);
    float* f2  = (float*)(sm + SM_F2);
    float* dea = (float*)(sm + SM_DEA);
    float* deb = (float*)(sm + SM_DEB);
    float* dec = (float*)(sm + SM_DEC);
    unsigned long long* emask = (unsigned long long*)(sm + SM_EMASK);
    unsigned long long* nmask = (unsigned long long*)(sm + SM_NMASK);
    float* resid = (float*)(sm + SM_RESID);

    // ---- Phase 0: gathers, x0 hi/lo image, 6-channel dots, masks ----
    for (int j = warp; j < 64; j += 32) {
        int tok = inputs[b * 64 + j];
        float4 v = ((const float4*)(emb + (size_t)tok * 128))[lane];
        ((float4*)resid)[j * 32 + lane] = v;
        float4 v2 = ((const float4*)(emb2 + (size_t)tok * 128))[lane];
        ((float4*)(out + 2 * BLD + ((size_t)b * 64 + j) * 128))[lane] = v2;
        st2(sm, SM_X + j * 272 + 8 * lane, 17408, v.x, v.y);
        st2(sm, SM_X + j * 272 + 8 * lane + 4, 17408, v.z, v.w);
        float vs[4] = {v.x, v.y, v.z, v.w};
        int k0 = 4 * lane;
        float p[6] = {0.f, 0.f, 0.f, 0.f, 0.f, 0.f};
        #pragma unroll
        for (int t = 0; t < 4; t++) {
            #pragma unroll
            for (int c = 0; c < 6; c++) p[c] += vs[t] * g_u[c][k0 + t];
        }
        #pragma unroll
        for (int c = 0; c < 6; c++) RADD(p[c]);
        if (lane == 0) {
            float e = g_c1[0] + p[0];
            e1v[j] = e > 0.f ? e : ALPHA * e;
            s2v[j] = p[1]; vv[j] = p[2];
            dxa[j] = p[3]; dxb[j] = p[4]; dxc[j] = p[5];
        }
    }
    for (int e = warp; e < 128; e += 32) {
        const float* row = HT + ((size_t)b * 128 + e) * 64;
        unsigned lo = __ballot_sync(FULL, row[lane] > 0.f);
        unsigned hi = __ballot_sync(FULL, row[lane + 32] > 0.f);
        if (lane == 0) emask[e] = (unsigned long long)lo | ((unsigned long long)hi << 32);
    }
    __syncthreads();
    if (tid < 64) {
        unsigned long long m0 = 0, m1 = 0;
        #pragma unroll 4
        for (int e = 0; e < 64; e++) {
            m0 |= ((emask[e] >> tid) & 1ull) << e;
            m1 |= ((emask[e + 64] >> tid) & 1ull) << e;
        }
        nmask[2 * tid] = m0; nmask[2 * tid + 1] = m1;
    }
    __syncthreads();

    for (int layer = 0; layer < 2; layer++) {
        // ---- att1[e][j] softmax + f2 channel (+de channels layer0) ----
        for (int e = warp; e < 128; e += 32) {
            unsigned long long m = emask[e];
            float w0, w1;
            if (m == 0ull) { w0 = w1 = 1.f / 64.f; }
            else {
                bool b0 = (m >> lane) & 1ull, b1 = (m >> (lane + 32)) & 1ull;
                float v0 = b0 ? e1v[lane] : -1e30f;
                float v1 = b1 ? e1v[lane + 32] : -1e30f;
                float mx = fmaxf(v0, v1); RMAX(mx);
                w0 = b0 ? __expf(v0 - mx) : 0.f;
                w1 = b1 ? __expf(v1 - mx) : 0.f;
                float s = w0 + w1; RADD(s);
                float inv = 1.f / s; w0 *= inv; w1 *= inv;
            }
            float t = w0 * vv[lane] + w1 * vv[lane + 32]; RADD(t);
            if (lane == 0) f2[e] = t;
            if (layer == 0) {
                t = w0 * dxa[lane] + w1 * dxa[lane + 32]; RADD(t); if (lane == 0) dea[e] = t;
                t = w0 * dxb[lane] + w1 * dxb[lane + 32]; RADD(t); if (lane == 0) deb[e] = t;
                t = w0 * dxc[lane] + w1 * dxc[lane + 32]; RADD(t); if (lane == 0) dec[e] = t;
            }
            st1(sm, SM_ATT1 + e * 144 + lane * 2, 18432, w0);
            st1(sm, SM_ATT1 + e * 144 + (lane + 32) * 2, 18432, w1);
        }
        __syncthreads();

        // ---- attN[j][e] softmax (+x1 channel updates layer0) ----
        for (int j = warp; j < 64; j += 32) {
            unsigned long long m0 = nmask[2 * j], m1 = nmask[2 * j + 1];
            float ss = s2v[j];
            float w[4];
            if ((m0 | m1) == 0ull) { w[0] = w[1] = w[2] = w[3] = 1.f / 128.f; }
            else {
                bool bt[4] = { (bool)((m0 >> lane) & 1ull), (bool)((m0 >> (lane + 32)) & 1ull),
                               (bool)((m1 >> lane) & 1ull), (bool)((m1 >> (lane + 32)) & 1ull) };
                float vx[4];
                #pragma unroll
                for (int t = 0; t < 4; t++) {
                    float v = ss + f2[lane + 32 * t];
                    v = v > 0.f ? v : ALPHA * v;
                    vx[t] = bt[t] ? v : -1e30f;
                }
                float mx = fmaxf(fmaxf(vx[0], vx[1]), fmaxf(vx[2], vx[3])); RMAX(mx);
                float s = 0.f;
                #pragma unroll
                for (int t = 0; t < 4; t++) { w[t] = bt[t] ? __expf(vx[t] - mx) : 0.f; s += w[t]; }
                RADD(s);
                float inv = 1.f / s;
                #pragma unroll
                for (int t = 0; t < 4; t++) w[t] *= inv;
            }
            if (layer == 0) {
                float ta = w[0]*dea[lane] + w[1]*dea[lane+32] + w[2]*dea[lane+64] + w[3]*dea[lane+96];
                float tb = w[0]*deb[lane] + w[1]*deb[lane+32] + w[2]*deb[lane+64] + w[3]*deb[lane+96];
                float tc = w[0]*dec[lane] + w[1]*dec[lane+32] + w[2]*dec[lane+64] + w[3]*dec[lane+96];
                RADD(ta); RADD(tb); RADD(tc);
                if (lane == 0) {
                    float x1a = g_c1[1] + ta + dxa[j];
                    e1v[j] = x1a > 0.f ? x1a : ALPHA * x1a;
                    s2v[j] = tb + dxb[j];
                    vv[j]  = tc + dxc[j];
                }
            }
            #pragma unroll
            for (int t = 0; t < 4; t++)
                st1(sm, SM_ATTN + j * 272 + (lane + 32 * t) * 2, 17408, w[t]);
        }
        __syncthreads();

        // ---- P = attN @ att1 : M64 K128 N64 ; warp = 4 mtiles x 8 n8 ----
        {
            int mt = warp >> 3, nt = warp & 7;
            float d[4] = {0.f, 0.f, 0.f, 0.f};
            uint32_t aHi = sbase + SM_ATTN + (mt * 16 + (lane & 15)) * 272 + (lane >> 4) * 16;
            uint32_t bHi = sbase + SM_ATT1 + (lane & 15) * 144 + nt * 16;
            #pragma unroll
            for (int k = 0; k < 8; k++) {
                uint32_t ah[4], al[4], bh[2], bl[2];
                ldm_x4(ah, aHi + k * 32);
                ldm_x4(al, aHi + 17408 + k * 32);
                ldm_x2t(bh, bHi + k * 2304);           // 16 rows * 144B
                ldm_x2t(bl, bHi + 18432 + k * 2304);
                mma16816(d, ah, bh);
                mma16816(d, ah, bl);
                mma16816(d, al, bh);
            }
            int r = mt * 16 + (lane >> 2), c = nt * 8 + (lane & 3) * 2;
            st2(sm, SM_P + r * 144 + c * 2, 9216, d[0], d[1]);
            st2(sm, SM_P + (r + 8) * 144 + c * 2, 9216, d[2], d[3]);
        }
        __syncthreads();

        if (layer == 0) {
            // ---- node0 = P @ x0 ; +resid -> x1 (into SM_X) ----
            int mt = warp >> 3, nc = warp & 7;
            float d[8] = {0.f, 0.f, 0.f, 0.f, 0.f, 0.f, 0.f, 0.f};
            uint32_t aHi = sbase + SM_P + (mt * 16 + (lane & 15)) * 144 + (lane >> 4) * 16;
            uint32_t bHi = sbase + SM_X + (lane & 15) * 272 + nc * 32 + (lane >> 4) * 16;
            #pragma unroll
            for (int k = 0; k < 4; k++) {
                uint32_t ah[4], al[4], bh[4], bl[4];
                ldm_x4(ah, aHi + k * 32);
                ldm_x4(al, aHi + 9216 + k * 32);
                ldm_x4t(bh, bHi + k * 4352);           // 16 rows * 272B
                ldm_x4t(bl, bHi + 17408 + k * 4352);
                mma16816(d, ah, bh); mma16816(d, ah, bl); mma16816(d, al, bh);
                mma16816(d + 4, ah, bh + 2); mma16816(d + 4, ah, bl + 2); mma16816(d + 4, al, bh + 2);
            }
            __syncthreads();  // all reads of SM_X done before overwriting
            int r = mt * 16 + (lane >> 2);
            #pragma unroll
            for (int t = 0; t < 2; t++) {
                int c = nc * 16 + t * 8 + (lane & 3) * 2;
                float v00 = d[t*4+0] + resid[r * 128 + c];
                float v01 = d[t*4+1] + resid[r * 128 + c + 1];
                float v10 = d[t*4+2] + resid[(r + 8) * 128 + c];
                float v11 = d[t*4+3] + resid[(r + 8) * 128 + c + 1];
                st2(sm, SM_X + r * 272 + c * 2, 17408, v00, v01);
                st2(sm, SM_X + (r + 8) * 272 + c * 2, 17408, v10, v11);
            }
            __syncthreads();
        } else {
            // ---- copy g2w image into SM_G2W (att buffers dead after P1) ----
            {
                const float4* src = (const float4*)g_w2img;
                float4* dst = (float4*)(sm + SM_G2W);
                for (int i = tid; i < 4352; i += 1024) dst[i] = src[i];
            }
            __syncthreads();
            // ---- y = P1 @ x1 -> SM_Y ----
            {
                int mt = warp >> 3, nc = warp & 7;
                float d[8] = {0.f, 0.f, 0.f, 0.f, 0.f, 0.f, 0.f, 0.f};
                uint32_t aHi = sbase + SM_P + (mt * 16 + (lane & 15)) * 144 + (lane >> 4) * 16;
                uint32_t bHi = sbase + SM_X + (lane & 15) * 272 + nc * 32 + (lane >> 4) * 16;
                #pragma unroll
                for (int k = 0; k < 4; k++) {
                    uint32_t ah[4], al[4], bh[4], bl[4];
                    ldm_x4(ah, aHi + k * 32);
                    ldm_x4(al, aHi + 9216 + k * 32);
                    ldm_x4t(bh, bHi + k * 4352);
                    ldm_x4t(bl, bHi + 17408 + k * 4352);
                    mma16816(d, ah, bh); mma16816(d, ah, bl); mma16816(d, al, bh);
                    mma16816(d + 4, ah, bh + 2); mma16816(d + 4, ah, bl + 2); mma16816(d + 4, al, bh + 2);
                }
                int r = mt * 16 + (lane >> 2);
                #pragma unroll
                for (int t = 0; t < 2; t++) {
                    int c = nc * 16 + t * 8 + (lane & 3) * 2;
                    st2(sm, SM_Y + r * 272 + c * 2, 17408, d[t*4+0], d[t*4+1]);
                    st2(sm, SM_Y + (r + 8) * 272 + c * 2, 17408, d[t*4+2], d[t*4+3]);
                }
            }
            __syncthreads();
            // ---- node1 = y @ g2w ; +resid -> resid (fp32) ----
            {
                int mt = warp >> 3, nc = warp & 7;
                float d[8] = {0.f, 0.f, 0.f, 0.f, 0.f, 0.f, 0.f, 0.f};
                uint32_t aHi = sbase + SM_Y + (mt * 16 + (lane & 15)) * 272 + (lane >> 4) * 16;
                uint32_t bHi = sbase + SM_G2W + (lane & 15) * 272 + nc * 32 + (lane >> 4) * 16;
                #pragma unroll
                for (int k = 0; k < 8; k++) {
                    uint32_t ah[4], al[4], bh[4], bl[4];
                    ldm_x4(ah, aHi + k * 32);
                    ldm_x4(al, aHi + 17408 + k * 32);
                    ldm_x4t(bh, bHi + k * 4352);
                    ldm_x4t(bl, bHi + 34816 + k * 4352);
                    mma16816(d, ah, bh); mma16816(d, ah, bl); mma16816(d, al, bh);
                    mma16816(d + 4, ah, bh + 2); mma16816(d + 4, ah, bl + 2); mma16816(d + 4, al, bh + 2);
                }
                int r = mt * 16 + (lane >> 2);
                #pragma unroll
                for (int t = 0; t < 2; t++) {
                    int c = nc * 16 + t * 8 + (lane & 3) * 2;
                    resid[r * 128 + c]           += d[t*4+0];
                    resid[r * 128 + c + 1]       += d[t*4+1];
                    resid[(r + 8) * 128 + c]     += d[t*4+2];
                    resid[(r + 8) * 128 + c + 1] += d[t*4+3];
                }
            }
            __syncthreads();
        }
    }

    // ---- Output: (x, x) from resid (now holds final x) ----
    for (int j = warp; j < 64; j += 32) {
        float4 v = ((const float4*)resid)[j * 32 + lane];
        ((float4*)(out + ((size_t)b * 64 + j) * 128))[lane] = v;
        ((float4*)(out + BLD + ((size_t)b * 64 + j) * 128))[lane] = v;
    }
}

extern "C" void kernel_launch(void* const* d_in, const int* in_sizes, int n_in,
                              void* d_out, int out_size)
{
    const int*   inputs = (const int*)d_in[0];
    const float* HT     = (const float*)d_in[1];
    const float* emb    = (const float*)d_in[4];
    const float* emb2   = (const float*)d_in[5];
    const float* g1_w2  = (const float*)d_in[6];
    const float* g1_w3  = (const float*)d_in[7];
    const float* g1_q   = (const float*)d_in[8];
    const float* g1_a   = (const float*)d_in[9];
    const float* g1_a2  = (const float*)d_in[10];
    const float* g2_w   = (const float*)d_in[11];
    const float* g2_w2  = (const float*)d_in[12];
    const float* g2_w3  = (const float*)d_in[13];
    const float* g2_q   = (const float*)d_in[14];
    const float* g2_a   = (const float*)d_in[15];
    const float* g2_a2  = (const float*)d_in[16];
    float* out = (float*)d_out;

    cudaFuncSetAttribute(session_kernel,
                         cudaFuncAttributeMaxDynamicSharedMemorySize, SMEM_BYTES);

    precompute_kernel<<<1, 256>>>(g1_w2, g1_w3, g1_q, g1_a, g1_a2,
                                  g2_w2, g2_w3, g2_q, g2_a, g2_a2, g2_w);
    img_kernel<<<64, 256>>>(g2_w);
    session_kernel<<<Bb, 1024, SMEM_BYTES>>>(inputs, HT, emb, emb2, out);
}

// round 7
// speedup vs baseline: 1.9469x; 1.3121x over previous
#include <cuda_runtime.h>
#include <cuda_bf16.h>
#include <cstdint>

#define FULL 0xFFFFFFFFu
constexpr int Bb = 512;
constexpr float ALPHA = 0.2f;

// ---------------- mma / ldmatrix helpers (baseline PTX, sm_80+) ----------------
__device__ __forceinline__ void mma16816(float* d, const uint32_t* a, const uint32_t* b) {
    asm volatile("mma.sync.aligned.m16n8k16.row.col.f32.bf16.bf16.f32 "
        "{%0,%1,%2,%3}, {%4,%5,%6,%7}, {%8,%9}, {%0,%1,%2,%3};"
        : "+f"(d[0]), "+f"(d[1]), "+f"(d[2]), "+f"(d[3])
        : "r"(a[0]), "r"(a[1]), "r"(a[2]), "r"(a[3]), "r"(b[0]), "r"(b[1]));
}
__device__ __forceinline__ void ldm_x4(uint32_t* r, uint32_t addr) {
    asm volatile("ldmatrix.sync.aligned.m8n8.x4.shared.b16 {%0,%1,%2,%3}, [%4];"
        : "=r"(r[0]), "=r"(r[1]), "=r"(r[2]), "=r"(r[3]) : "r"(addr));
}
__device__ __forceinline__ void ldm_x4t(uint32_t* r, uint32_t addr) {
    asm volatile("ldmatrix.sync.aligned.m8n8.x4.trans.shared.b16 {%0,%1,%2,%3}, [%4];"
        : "=r"(r[0]), "=r"(r[1]), "=r"(r[2]), "=r"(r[3]) : "r"(addr));
}
__device__ __forceinline__ void ldm_x2t(uint32_t* r, uint32_t addr) {
    asm volatile("ldmatrix.sync.aligned.m8n8.x2.trans.shared.b16 {%0,%1}, [%2];"
        : "=r"(r[0]), "=r"(r[1]) : "r"(addr));
}
__device__ __forceinline__ uint32_t smem_u32(const void* p) {
    uint32_t a;
    asm("{ .reg .u64 t; cvta.to.shared.u64 t, %1; cvt.u32.u64 %0, t; }" : "=r"(a) : "l"(p));
    return a;
}

#define RADD(v) { _Pragma("unroll") for (int _o = 16; _o; _o >>= 1) v += __shfl_xor_sync(FULL, v, _o); }
#define RMAX(v) { _Pragma("unroll") for (int _o = 16; _o; _o >>= 1) v = fmaxf(v, __shfl_xor_sync(FULL, v, _o)); }

// ---------------- precomputed globals ----------------
// g_u: 0=u1a 1=u2a 2=u3a 3=u1b 4=u2b 5=u3g(=g2w@u3b)
__device__ float g_u[6][128];
__device__ float g_u3b[128];
__device__ float g_c1[2];
// g2w as bf16 hi[128][136] | lo[128][136] (row=k, col=d), 69632 bytes
__device__ __align__(16) uint8_t g_w2img[69632];

// grid (2, 128) x 128 threads: block (layer, k) computes u1,u2,u3 dots in parallel
__global__ void precompute_kernel(
    const float* __restrict__ w2a, const float* __restrict__ w3a,
    const float* __restrict__ qa,  const float* __restrict__ aa,
    const float* __restrict__ a2a,
    const float* __restrict__ w2b, const float* __restrict__ w3b,
    const float* __restrict__ qb,  const float* __restrict__ ab,
    const float* __restrict__ a2b)
{
    const int layer = blockIdx.x;
    const int k     = blockIdx.y;
    const int c     = threadIdx.x;         // 0..127
    const int wp    = c >> 5, ln = c & 31;
    const float* w2 = layer ? w2b : w2a;
    const float* w3 = layer ? w3b : w3a;
    const float* q  = layer ? qb  : qa;
    const float* a  = layer ? ab  : aa;
    const float* a2 = layer ? a2b : a2a;

    float w2v = w2[k * 128 + c];
    float p1 = w2v * a[128 + c];
    float p2 = w2v * a2[c];
    float p3 = w3[k * 128 + c] * a2[128 + c];
    float p4 = (k == 0) ? q[c] * a[c] : 0.f;
    RADD(p1); RADD(p2); RADD(p3); RADD(p4);
    __shared__ float sh[4][4];
    if (ln == 0) { sh[0][wp] = p1; sh[1][wp] = p2; sh[2][wp] = p3; sh[3][wp] = p4; }
    __syncthreads();
    if (c == 0) {
        float u1 = sh[0][0] + sh[0][1] + sh[0][2] + sh[0][3];
        float u2 = sh[1][0] + sh[1][1] + sh[1][2] + sh[1][3];
        float u3 = sh[2][0] + sh[2][1] + sh[2][2] + sh[2][3];
        if (layer == 0) { g_u[0][k] = u1; g_u[1][k] = u2; g_u[2][k] = u3; }
        else            { g_u[3][k] = u1; g_u[4][k] = u2; g_u3b[k] = u3; }
        if (k == 0) g_c1[layer] = sh[3][0] + sh[3][1] + sh[3][2] + sh[3][3];
    }
}

// 64 blocks x 256 threads: convert g2w -> hi/lo image; warps 0..127 also do u3g
__global__ void img_kernel(const float* __restrict__ g2w) {
    int idx = blockIdx.x * 256 + threadIdx.x;  // 16384
    int kk = idx >> 7, d = idx & 127;
    float v = g2w[kk * 128 + d];
    __nv_bfloat16 h = __float2bfloat16(v);
    *(__nv_bfloat16*)(g_w2img + (kk * 136 + d) * 2) = h;
    *(__nv_bfloat16*)(g_w2img + 34816 + (kk * 136 + d) * 2) =
        __float2bfloat16(v - __bfloat162float(h));
    int gw = blockIdx.x * 8 + (threadIdx.x >> 5);
    if (gw < 128) {
        int ln = threadIdx.x & 31;
        float s = 0.f;
        #pragma unroll
        for (int t = 0; t < 4; t++)
            s += g2w[gw * 128 + ln + 32 * t] * g_u3b[ln + 32 * t];
        RADD(s);
        if (ln == 0) g_u[5][gw] = s;
    }
}

// ---------------- smem layout (bytes) ----------------
constexpr int SM_ATT1  = 0;        // hi [128][72] 18432 | lo +18432 ; 36864
constexpr int SM_ATTN  = 36864;    // hi [64][136] 17408 | lo +17408 ; 34816
constexpr int SM_G2W   = 0;        // 69632 (overlaps ATT1+ATTN; layer1 only, after P1)
constexpr int SM_X     = 71680;    // hi [64][136] | lo ; 34816
constexpr int SM_Y     = 106496;   // hi [64][136] | lo ; 34816
constexpr int SM_P     = 141312;   // hi [64][72] 9216 | lo ; 18432
constexpr int SM_RESID = 159744;   // fp32 [64][128] 32768
constexpr int SM_E1V   = 192512;
constexpr int SM_S2    = 192768;
constexpr int SM_VV    = 193024;
constexpr int SM_DXA   = 193280;
constexpr int SM_DXB   = 193536;
constexpr int SM_DXC   = 193792;
constexpr int SM_F2    = 194048;
constexpr int SM_DEA   = 194560;
constexpr int SM_DEB   = 195072;
constexpr int SM_DEC   = 195584;
constexpr int SM_EMASK = 196096;   // 128 u64
constexpr int SM_NMASK = 197120;   // 64 x 2 u64
constexpr int SMEM_BYTES = 198144;

__device__ __forceinline__ void st2(uint8_t* sm, int off, int loB, float a, float b) {
    __nv_bfloat16 h0 = __float2bfloat16(a), h1 = __float2bfloat16(b);
    *(__nv_bfloat162*)(sm + off) = __halves2bfloat162(h0, h1);
    *(__nv_bfloat162*)(sm + off + loB) = __floats2bfloat162_rn(
        a - __bfloat162float(h0), b - __bfloat162float(h1));
}
__device__ __forceinline__ void st1(uint8_t* sm, int off, int loB, float a) {
    __nv_bfloat16 h = __float2bfloat16(a);
    *(__nv_bfloat16*)(sm + off) = h;
    *(__nv_bfloat16*)(sm + off + loB) = __float2bfloat16(a - __bfloat162float(h));
}

__global__ __launch_bounds__(1024, 1) void session_kernel(
    const int*   __restrict__ inputs,
    const float* __restrict__ HT,
    const float* __restrict__ emb,
    const float* __restrict__ emb2,
    float*       __restrict__ out)
{
    extern __shared__ __align__(16) uint8_t sm[];
    const int tid  = threadIdx.x;
    const int warp = tid >> 5;
    const int lane = tid & 31;
    const int b    = blockIdx.x;
    const size_t BLD = (size_t)Bb * 64 * 128;
    uint32_t sbase = smem_u32(sm);

    float* e1v = (float*)(sm + SM_E1V);
    float* s2v = (float*)(sm + SM_S2);
    float* vv  = (float*)(sm + SM_VV);
    float* dxa = (float*)(sm + SM_DXA);
    float* dxb = (float*)(sm + SM_DXB);
    float* dxc = (float*)(sm + SM_DXC);
    float* f2  = (float*)(sm + SM_F2);
    float* dea = (float*)(sm + SM_DEA);
    float* deb = (float*)(sm + SM_DEB);
    float* dec = (float*)(sm + SM_DEC);
    unsigned long long* emask = (unsigned long long*)(sm + SM_EMASK);
    unsigned long long* nmask = (unsigned long long*)(sm + SM_NMASK);
    float* resid = (float*)(sm + SM_RESID);

    // ---- Phase 0: gathers, x0 hi/lo image, 6-channel dots, masks ----
    for (int j = warp; j < 64; j += 32) {
        int tok = inputs[b * 64 + j];
        float4 v = ((const float4*)(emb + (size_t)tok * 128))[lane];
        ((float4*)resid)[j * 32 + lane] = v;
        float4 v2 = ((const float4*)(emb2 + (size_t)tok * 128))[lane];
        ((float4*)(out + 2 * BLD + ((size_t)b * 64 + j) * 128))[lane] = v2;
        st2(sm, SM_X + j * 272 + 8 * lane, 17408, v.x, v.y);
        st2(sm, SM_X + j * 272 + 8 * lane + 4, 17408, v.z, v.w);
        float vs[4] = {v.x, v.y, v.z, v.w};
        int k0 = 4 * lane;
        float p[6] = {0.f, 0.f, 0.f, 0.f, 0.f, 0.f};
        #pragma unroll
        for (int t = 0; t < 4; t++) {
            #pragma unroll
            for (int c = 0; c < 6; c++) p[c] += vs[t] * g_u[c][k0 + t];
        }
        #pragma unroll
        for (int c = 0; c < 6; c++) RADD(p[c]);
        if (lane == 0) {
            float e = g_c1[0] + p[0];
            e1v[j] = e > 0.f ? e : ALPHA * e;
            s2v[j] = p[1]; vv[j] = p[2];
            dxa[j] = p[3]; dxb[j] = p[4]; dxc[j] = p[5];
        }
    }
    for (int e = warp; e < 128; e += 32) {
        const float* row = HT + ((size_t)b * 128 + e) * 64;
        unsigned lo = __ballot_sync(FULL, row[lane] > 0.f);
        unsigned hi = __ballot_sync(FULL, row[lane + 32] > 0.f);
        if (lane == 0) emask[e] = (unsigned long long)lo | ((unsigned long long)hi << 32);
    }
    __syncthreads();
    if (tid < 64) {
        unsigned long long m0 = 0, m1 = 0;
        #pragma unroll 4
        for (int e = 0; e < 64; e++) {
            m0 |= ((emask[e] >> tid) & 1ull) << e;
            m1 |= ((emask[e + 64] >> tid) & 1ull) << e;
        }
        nmask[2 * tid] = m0; nmask[2 * tid + 1] = m1;
    }
    __syncthreads();

    for (int layer = 0; layer < 2; layer++) {
        // ---- att1[e][j] softmax + f2 channel (+de channels layer0) ----
        for (int e = warp; e < 128; e += 32) {
            unsigned long long m = emask[e];
            float w0, w1;
            if (m == 0ull) { w0 = w1 = 1.f / 64.f; }
            else {
                bool b0 = (m >> lane) & 1ull, b1 = (m >> (lane + 32)) & 1ull;
                float v0 = b0 ? e1v[lane] : -1e30f;
                float v1 = b1 ? e1v[lane + 32] : -1e30f;
                float mx = fmaxf(v0, v1); RMAX(mx);
                w0 = b0 ? __expf(v0 - mx) : 0.f;
                w1 = b1 ? __expf(v1 - mx) : 0.f;
                float s = w0 + w1; RADD(s);
                float inv = 1.f / s; w0 *= inv; w1 *= inv;
            }
            float t = w0 * vv[lane] + w1 * vv[lane + 32]; RADD(t);
            if (lane == 0) f2[e] = t;
            if (layer == 0) {
                t = w0 * dxa[lane] + w1 * dxa[lane + 32]; RADD(t); if (lane == 0) dea[e] = t;
                t = w0 * dxb[lane] + w1 * dxb[lane + 32]; RADD(t); if (lane == 0) deb[e] = t;
                t = w0 * dxc[lane] + w1 * dxc[lane + 32]; RADD(t); if (lane == 0) dec[e] = t;
            }
            st1(sm, SM_ATT1 + e * 144 + lane * 2, 18432, w0);
            st1(sm, SM_ATT1 + e * 144 + (lane + 32) * 2, 18432, w1);
        }
        __syncthreads();

        // ---- attN[j][e] softmax (+x1 channel updates layer0) ----
        for (int j = warp; j < 64; j += 32) {
            unsigned long long m0 = nmask[2 * j], m1 = nmask[2 * j + 1];
            float ss = s2v[j];
            float w[4];
            if ((m0 | m1) == 0ull) { w[0] = w[1] = w[2] = w[3] = 1.f / 128.f; }
            else {
                bool bt[4] = { (bool)((m0 >> lane) & 1ull), (bool)((m0 >> (lane + 32)) & 1ull),
                               (bool)((m1 >> lane) & 1ull), (bool)((m1 >> (lane + 32)) & 1ull) };
                float vx[4];
                #pragma unroll
                for (int t = 0; t < 4; t++) {
                    float v = ss + f2[lane + 32 * t];
                    v = v > 0.f ? v : ALPHA * v;
                    vx[t] = bt[t] ? v : -1e30f;
                }
                float mx = fmaxf(fmaxf(vx[0], vx[1]), fmaxf(vx[2], vx[3])); RMAX(mx);
                float s = 0.f;
                #pragma unroll
                for (int t = 0; t < 4; t++) { w[t] = bt[t] ? __expf(vx[t] - mx) : 0.f; s += w[t]; }
                RADD(s);
                float inv = 1.f / s;
                #pragma unroll
                for (int t = 0; t < 4; t++) w[t] *= inv;
            }
            if (layer == 0) {
                float ta = w[0]*dea[lane] + w[1]*dea[lane+32] + w[2]*dea[lane+64] + w[3]*dea[lane+96];
                float tb = w[0]*deb[lane] + w[1]*deb[lane+32] + w[2]*deb[lane+64] + w[3]*deb[lane+96];
                float tc = w[0]*dec[lane] + w[1]*dec[lane+32] + w[2]*dec[lane+64] + w[3]*dec[lane+96];
                RADD(ta); RADD(tb); RADD(tc);
                if (lane == 0) {
                    float x1a = g_c1[1] + ta + dxa[j];
                    e1v[j] = x1a > 0.f ? x1a : ALPHA * x1a;
                    s2v[j] = tb + dxb[j];
                    vv[j]  = tc + dxc[j];
                }
            }
            #pragma unroll
            for (int t = 0; t < 4; t++)
                st1(sm, SM_ATTN + j * 272 + (lane + 32 * t) * 2, 17408, w[t]);
        }
        __syncthreads();

        // ---- P = attN @ att1 : M64 K128 N64 ----
        {
            int mt = warp >> 3, nt = warp & 7;
            float d[4] = {0.f, 0.f, 0.f, 0.f};
            uint32_t aHi = sbase + SM_ATTN + (mt * 16 + (lane & 15)) * 272 + (lane >> 4) * 16;
            uint32_t bHi = sbase + SM_ATT1 + (lane & 15) * 144 + nt * 16;
            #pragma unroll
            for (int k = 0; k < 8; k++) {
                uint32_t ah[4], al[4], bh[2], bl[2];
                ldm_x4(ah, aHi + k * 32);
                ldm_x4(al, aHi + 17408 + k * 32);
                ldm_x2t(bh, bHi + k * 2304);
                ldm_x2t(bl, bHi + 18432 + k * 2304);
                mma16816(d, ah, bh);
                mma16816(d, ah, bl);
                mma16816(d, al, bh);
            }
            int r = mt * 16 + (lane >> 2), c = nt * 8 + (lane & 3) * 2;
            st2(sm, SM_P + r * 144 + c * 2, 9216, d[0], d[1]);
            st2(sm, SM_P + (r + 8) * 144 + c * 2, 9216, d[2], d[3]);
        }
        __syncthreads();

        if (layer == 0) {
            // ---- node0 = P @ x0 ; +resid -> x1 (into SM_X) ----
            int mt = warp >> 3, nc = warp & 7;
            float d[8] = {0.f, 0.f, 0.f, 0.f, 0.f, 0.f, 0.f, 0.f};
            uint32_t aHi = sbase + SM_P + (mt * 16 + (lane & 15)) * 144 + (lane >> 4) * 16;
            uint32_t bHi = sbase + SM_X + (lane & 15) * 272 + nc * 32 + (lane >> 4) * 16;
            #pragma unroll
            for (int k = 0; k < 4; k++) {
                uint32_t ah[4], al[4], bh[4], bl[4];
                ldm_x4(ah, aHi + k * 32);
                ldm_x4(al, aHi + 9216 + k * 32);
                ldm_x4t(bh, bHi + k * 4352);
                ldm_x4t(bl, bHi + 17408 + k * 4352);
                mma16816(d, ah, bh); mma16816(d, ah, bl); mma16816(d, al, bh);
                mma16816(d + 4, ah, bh + 2); mma16816(d + 4, ah, bl + 2); mma16816(d + 4, al, bh + 2);
            }
            __syncthreads();
            int r = mt * 16 + (lane >> 2);
            #pragma unroll
            for (int t = 0; t < 2; t++) {
                int c = nc * 16 + t * 8 + (lane & 3) * 2;
                float v00 = d[t*4+0] + resid[r * 128 + c];
                float v01 = d[t*4+1] + resid[r * 128 + c + 1];
                float v10 = d[t*4+2] + resid[(r + 8) * 128 + c];
                float v11 = d[t*4+3] + resid[(r + 8) * 128 + c + 1];
                st2(sm, SM_X + r * 272 + c * 2, 17408, v00, v01);
                st2(sm, SM_X + (r + 8) * 272 + c * 2, 17408, v10, v11);
            }
            __syncthreads();
        } else {
            // ---- copy g2w image into SM_G2W ----
            {
                const float4* src = (const float4*)g_w2img;
                float4* dst = (float4*)(sm + SM_G2W);
                for (int i = tid; i < 4352; i += 1024) dst[i] = src[i];
            }
            __syncthreads();
            // ---- y = P1 @ x1 -> SM_Y ----
            {
                int mt = warp >> 3, nc = warp & 7;
                float d[8] = {0.f, 0.f, 0.f, 0.f, 0.f, 0.f, 0.f, 0.f};
                uint32_t aHi = sbase + SM_P + (mt * 16 + (lane & 15)) * 144 + (lane >> 4) * 16;
                uint32_t bHi = sbase + SM_X + (lane & 15) * 272 + nc * 32 + (lane >> 4) * 16;
                #pragma unroll
                for (int k = 0; k < 4; k++) {
                    uint32_t ah[4], al[4], bh[4], bl[4];
                    ldm_x4(ah, aHi + k * 32);
                    ldm_x4(al, aHi + 9216 + k * 32);
                    ldm_x4t(bh, bHi + k * 4352);
                    ldm_x4t(bl, bHi + 17408 + k * 4352);
                    mma16816(d, ah, bh); mma16816(d, ah, bl); mma16816(d, al, bh);
                    mma16816(d + 4, ah, bh + 2); mma16816(d + 4, ah, bl + 2); mma16816(d + 4, al, bh + 2);
                }
                int r = mt * 16 + (lane >> 2);
                #pragma unroll
                for (int t = 0; t < 2; t++) {
                    int c = nc * 16 + t * 8 + (lane & 3) * 2;
                    st2(sm, SM_Y + r * 272 + c * 2, 17408, d[t*4+0], d[t*4+1]);
                    st2(sm, SM_Y + (r + 8) * 272 + c * 2, 17408, d[t*4+2], d[t*4+3]);
                }
            }
            __syncthreads();
            // ---- node1 = y @ g2w ; +resid -> resid (fp32) ----
            {
                int mt = warp >> 3, nc = warp & 7;
                float d[8] = {0.f, 0.f, 0.f, 0.f, 0.f, 0.f, 0.f, 0.f};
                uint32_t aHi = sbase + SM_Y + (mt * 16 + (lane & 15)) * 272 + (lane >> 4) * 16;
                uint32_t bHi = sbase + SM_G2W + (lane & 15) * 272 + nc * 32 + (lane >> 4) * 16;
                #pragma unroll
                for (int k = 0; k < 8; k++) {
                    uint32_t ah[4], al[4], bh[4], bl[4];
                    ldm_x4(ah, aHi + k * 32);
                    ldm_x4(al, aHi + 17408 + k * 32);
                    ldm_x4t(bh, bHi + k * 4352);
                    ldm_x4t(bl, bHi + 34816 + k * 4352);
                    mma16816(d, ah, bh); mma16816(d, ah, bl); mma16816(d, al, bh);
                    mma16816(d + 4, ah, bh + 2); mma16816(d + 4, ah, bl + 2); mma16816(d + 4, al, bh + 2);
                }
                int r = mt * 16 + (lane >> 2);
                #pragma unroll
                for (int t = 0; t < 2; t++) {
                    int c = nc * 16 + t * 8 + (lane & 3) * 2;
                    resid[r * 128 + c]           += d[t*4+0];
                    resid[r * 128 + c + 1]       += d[t*4+1];
                    resid[(r + 8) * 128 + c]     += d[t*4+2];
                    resid[(r + 8) * 128 + c + 1] += d[t*4+3];
                }
            }
            __syncthreads();
        }
    }

    // ---- Output: (x, x) from resid ----
    for (int j = warp; j < 64; j += 32) {
        float4 v = ((const float4*)resid)[j * 32 + lane];
        ((float4*)(out + ((size_t)b * 64 + j) * 128))[lane] = v;
        ((float4*)(out + BLD + ((size_t)b * 64 + j) * 128))[lane] = v;
    }
}

extern "C" void kernel_launch(void* const* d_in, const int* in_sizes, int n_in,
                              void* d_out, int out_size)
{
    const int*   inputs = (const int*)d_in[0];
    const float* HT     = (const float*)d_in[1];
    const float* emb    = (const float*)d_in[4];
    const float* emb2   = (const float*)d_in[5];
    const float* g1_w2  = (const float*)d_in[6];
    const float* g1_w3  = (const float*)d_in[7];
    const float* g1_q   = (const float*)d_in[8];
    const float* g1_a   = (const float*)d_in[9];
    const float* g1_a2  = (const float*)d_in[10];
    const float* g2_w   = (const float*)d_in[11];
    const float* g2_w2  = (const float*)d_in[12];
    const float* g2_w3  = (const float*)d_in[13];
    const float* g2_q   = (const float*)d_in[14];
    const float* g2_a   = (const float*)d_in[15];
    const float* g2_a2  = (const float*)d_in[16];
    float* out = (float*)d_out;

    cudaFuncSetAttribute(session_kernel,
                         cudaFuncAttributeMaxDynamicSharedMemorySize, SMEM_BYTES);

    precompute_kernel<<<dim3(2, 128), 128>>>(g1_w2, g1_w3, g1_q, g1_a, g1_a2,
                                             g2_w2, g2_w3, g2_q, g2_a, g2_a2);
    img_kernel<<<64, 256>>>(g2_w);
    session_kernel<<<Bb, 1024, SMEM_BYTES>>>(inputs, HT, emb, emb2, out);
}

// round 8
// speedup vs baseline: 2.1593x; 1.1091x over previous
#include <cuda_runtime.h>
#include <cuda_bf16.h>
#include <cstdint>

#define FULL 0xFFFFFFFFu
constexpr int Bb = 512;
constexpr float ALPHA = 0.2f;

// ---------------- mma / ldmatrix helpers (baseline PTX, sm_80+) ----------------
__device__ __forceinline__ void mma16816(float* d, const uint32_t* a, const uint32_t* b) {
    asm volatile("mma.sync.aligned.m16n8k16.row.col.f32.bf16.bf16.f32 "
        "{%0,%1,%2,%3}, {%4,%5,%6,%7}, {%8,%9}, {%0,%1,%2,%3};"
        : "+f"(d[0]), "+f"(d[1]), "+f"(d[2]), "+f"(d[3])
        : "r"(a[0]), "r"(a[1]), "r"(a[2]), "r"(a[3]), "r"(b[0]), "r"(b[1]));
}
__device__ __forceinline__ void ldm_x4(uint32_t* r, uint32_t addr) {
    asm volatile("ldmatrix.sync.aligned.m8n8.x4.shared.b16 {%0,%1,%2,%3}, [%4];"
        : "=r"(r[0]), "=r"(r[1]), "=r"(r[2]), "=r"(r[3]) : "r"(addr));
}
__device__ __forceinline__ void ldm_x4t(uint32_t* r, uint32_t addr) {
    asm volatile("ldmatrix.sync.aligned.m8n8.x4.trans.shared.b16 {%0,%1,%2,%3}, [%4];"
        : "=r"(r[0]), "=r"(r[1]), "=r"(r[2]), "=r"(r[3]) : "r"(addr));
}
__device__ __forceinline__ void ldm_x2t(uint32_t* r, uint32_t addr) {
    asm volatile("ldmatrix.sync.aligned.m8n8.x2.trans.shared.b16 {%0,%1}, [%2];"
        : "=r"(r[0]), "=r"(r[1]) : "r"(addr));
}
__device__ __forceinline__ uint32_t smem_u32(const void* p) {
    uint32_t a;
    asm("{ .reg .u64 t; cvta.to.shared.u64 t, %1; cvt.u32.u64 %0, t; }" : "=r"(a) : "l"(p));
    return a;
}

#define RADD(v) { _Pragma("unroll") for (int _o = 16; _o; _o >>= 1) v += __shfl_xor_sync(FULL, v, _o); }

// ---------------- precomputed globals ----------------
// g_u: 0=u1a 1=u2a 2=u3a 3=u1b 4=u2b 5=u3g(=g2w@u3b)
__device__ float g_u[6][128];
__device__ float g_u3b[128];
__device__ float g_c1[2];
// g2w as bf16 hi[128][136] | lo[128][136] (row=k, col=d), 69632 bytes
__device__ __align__(16) uint8_t g_w2img[69632];

// grid (2, 128) x 128 threads
__global__ void precompute_kernel(
    const float* __restrict__ w2a, const float* __restrict__ w3a,
    const float* __restrict__ qa,  const float* __restrict__ aa,
    const float* __restrict__ a2a,
    const float* __restrict__ w2b, const float* __restrict__ w3b,
    const float* __restrict__ qb,  const float* __restrict__ ab,
    const float* __restrict__ a2b)
{
    const int layer = blockIdx.x;
    const int k     = blockIdx.y;
    const int c     = threadIdx.x;
    const int wp    = c >> 5, ln = c & 31;
    const float* w2 = layer ? w2b : w2a;
    const float* w3 = layer ? w3b : w3a;
    const float* q  = layer ? qb  : qa;
    const float* a  = layer ? ab  : aa;
    const float* a2 = layer ? a2b : a2a;

    float w2v = w2[k * 128 + c];
    float p1 = w2v * a[128 + c];
    float p2 = w2v * a2[c];
    float p3 = w3[k * 128 + c] * a2[128 + c];
    float p4 = (k == 0) ? q[c] * a[c] : 0.f;
    RADD(p1); RADD(p2); RADD(p3); RADD(p4);
    __shared__ float sh[4][4];
    if (ln == 0) { sh[0][wp] = p1; sh[1][wp] = p2; sh[2][wp] = p3; sh[3][wp] = p4; }
    __syncthreads();
    if (c == 0) {
        float u1 = sh[0][0] + sh[0][1] + sh[0][2] + sh[0][3];
        float u2 = sh[1][0] + sh[1][1] + sh[1][2] + sh[1][3];
        float u3 = sh[2][0] + sh[2][1] + sh[2][2] + sh[2][3];
        if (layer == 0) { g_u[0][k] = u1; g_u[1][k] = u2; g_u[2][k] = u3; }
        else            { g_u[3][k] = u1; g_u[4][k] = u2; g_u3b[k] = u3; }
        if (k == 0) g_c1[layer] = sh[3][0] + sh[3][1] + sh[3][2] + sh[3][3];
    }
}

// 64 blocks x 256 threads
__global__ void img_kernel(const float* __restrict__ g2w) {
    int idx = blockIdx.x * 256 + threadIdx.x;
    int kk = idx >> 7, d = idx & 127;
    float v = g2w[kk * 128 + d];
    __nv_bfloat16 h = __float2bfloat16(v);
    *(__nv_bfloat16*)(g_w2img + (kk * 136 + d) * 2) = h;
    *(__nv_bfloat16*)(g_w2img + 34816 + (kk * 136 + d) * 2) =
        __float2bfloat16(v - __bfloat162float(h));
    int gw = blockIdx.x * 8 + (threadIdx.x >> 5);
    if (gw < 128) {
        int ln = threadIdx.x & 31;
        float s = 0.f;
        #pragma unroll
        for (int t = 0; t < 4; t++)
            s += g2w[gw * 128 + ln + 32 * t] * g_u3b[ln + 32 * t];
        RADD(s);
        if (ln == 0) g_u[5][gw] = s;
    }
}

// ---------------- smem layout (bytes) ----------------
constexpr int SM_ATT1  = 0;        // hi [128][72] | lo +18432 ; 36864
constexpr int SM_ATTN  = 36864;    // hi [64][136] | lo +17408 ; 34816
constexpr int SM_G2W   = 0;        // 69632 (overlaps ATT1+ATTN; layer1 after P1)
constexpr int SM_X     = 71680;    // hi [64][136] | lo ; 34816
constexpr int SM_Y     = 106496;   // hi [64][136] | lo ; 34816
constexpr int SM_P     = 141312;   // hi [64][72] | lo ; 18432
constexpr int SM_RESID = 159744;   // fp32 [64][128] 32768
constexpr int SM_E1V   = 192512;
constexpr int SM_S2    = 192768;
constexpr int SM_VV    = 193024;
constexpr int SM_DXA   = 193280;
constexpr int SM_DXB   = 193536;
constexpr int SM_DXC   = 193792;
constexpr int SM_F2    = 194048;
constexpr int SM_DEA   = 194560;
constexpr int SM_DEB   = 195072;
constexpr int SM_DEC   = 195584;
constexpr int SM_EMASK = 196096;   // 128 u64
constexpr int SM_NMASK = 197120;   // 64 x 2 u64
constexpr int SMEM_BYTES = 198144;

__device__ __forceinline__ void st2(uint8_t* sm, int off, int loB, float a, float b) {
    __nv_bfloat16 h0 = __float2bfloat16(a), h1 = __float2bfloat16(b);
    *(__nv_bfloat162*)(sm + off) = __halves2bfloat162(h0, h1);
    *(__nv_bfloat162*)(sm + off + loB) = __floats2bfloat162_rn(
        a - __bfloat162float(h0), b - __bfloat162float(h1));
}
__device__ __forceinline__ void st1(uint8_t* sm, int off, int loB, float a) {
    __nv_bfloat16 h = __float2bfloat16(a);
    *(__nv_bfloat16*)(sm + off) = h;
    *(__nv_bfloat16*)(sm + off + loB) = __float2bfloat16(a - __bfloat162float(h));
}

__global__ __launch_bounds__(1024, 1) void session_kernel(
    const int*   __restrict__ inputs,
    const float* __restrict__ HT,
    const float* __restrict__ emb,
    const float* __restrict__ emb2,
    float*       __restrict__ out)
{
    extern __shared__ __align__(16) uint8_t sm[];
    const int tid  = threadIdx.x;
    const int warp = tid >> 5;
    const int lane = tid & 31;
    const int b    = blockIdx.x;
    const size_t BLD = (size_t)Bb * 64 * 128;
    uint32_t sbase = smem_u32(sm);

    float* e1v = (float*)(sm + SM_E1V);
    float* s2v = (float*)(sm + SM_S2);
    float* vv  = (float*)(sm + SM_VV);
    float* dxa = (float*)(sm + SM_DXA);
    float* dxb = (float*)(sm + SM_DXB);
    float* dxc = (float*)(sm + SM_DXC);
    float* f2  = (float*)(sm + SM_F2);
    float* dea = (float*)(sm + SM_DEA);
    float* deb = (float*)(sm + SM_DEB);
    float* dec = (float*)(sm + SM_DEC);
    unsigned long long* emask = (unsigned long long*)(sm + SM_EMASK);
    unsigned long long* nmask = (unsigned long long*)(sm + SM_NMASK);
    float* resid = (float*)(sm + SM_RESID);

    // ---- Phase 0: gathers, x0 hi/lo image, 6-channel dots, masks ----
    for (int j = warp; j < 64; j += 32) {
        int tok = inputs[b * 64 + j];
        float4 v = ((const float4*)(emb + (size_t)tok * 128))[lane];
        ((float4*)resid)[j * 32 + lane] = v;
        float4 v2 = ((const float4*)(emb2 + (size_t)tok * 128))[lane];
        ((float4*)(out + 2 * BLD + ((size_t)b * 64 + j) * 128))[lane] = v2;
        st2(sm, SM_X + j * 272 + 8 * lane, 17408, v.x, v.y);
        st2(sm, SM_X + j * 272 + 8 * lane + 4, 17408, v.z, v.w);
        float p[6];
        #pragma unroll
        for (int c = 0; c < 6; c++) {
            float4 gu = ((const float4*)g_u[c])[lane];
            p[c] = v.x * gu.x + v.y * gu.y + v.z * gu.z + v.w * gu.w;
        }
        #pragma unroll
        for (int c = 0; c < 6; c++) RADD(p[c]);
        if (lane == 0) {
            float e = g_c1[0] + p[0];
            e1v[j] = e > 0.f ? e : ALPHA * e;
            s2v[j] = p[1]; vv[j] = p[2];
            dxa[j] = p[3]; dxb[j] = p[4]; dxc[j] = p[5];
        }
    }
    for (int e = warp; e < 128; e += 32) {
        const float* row = HT + ((size_t)b * 128 + e) * 64;
        unsigned lo = __ballot_sync(FULL, row[lane] > 0.f);
        unsigned hi = __ballot_sync(FULL, row[lane + 32] > 0.f);
        if (lane == 0) emask[e] = (unsigned long long)lo | ((unsigned long long)hi << 32);
    }
    __syncthreads();
    // nmask via ballot-transpose: each warp builds 2 nodes
    {
        unsigned long long eA = emask[lane],      eB = emask[lane + 32];
        unsigned long long eC = emask[lane + 64], eD = emask[lane + 96];
        #pragma unroll
        for (int t = 0; t < 2; t++) {
            int j = warp + 32 * t;
            unsigned b0 = __ballot_sync(FULL, (eA >> j) & 1ull);
            unsigned b1 = __ballot_sync(FULL, (eB >> j) & 1ull);
            unsigned b2 = __ballot_sync(FULL, (eC >> j) & 1ull);
            unsigned b3 = __ballot_sync(FULL, (eD >> j) & 1ull);
            if (lane == 0) {
                nmask[2 * j]     = (unsigned long long)b0 | ((unsigned long long)b1 << 32);
                nmask[2 * j + 1] = (unsigned long long)b2 | ((unsigned long long)b3 << 32);
            }
        }
    }
    __syncthreads();

    for (int layer = 0; layer < 2; layer++) {
        // ---- att1[e][j] softmax (no max-sub; logits tiny) + channels ----
        for (int e = warp; e < 128; e += 32) {
            unsigned long long m = emask[e];
            float w0, w1;
            if (m == 0ull) { w0 = w1 = 1.f / 64.f; }
            else {
                bool b0 = (m >> lane) & 1ull, b1 = (m >> (lane + 32)) & 1ull;
                w0 = b0 ? __expf(e1v[lane]) : 0.f;
                w1 = b1 ? __expf(e1v[lane + 32]) : 0.f;
                float s = w0 + w1; RADD(s);
                float inv = 1.f / s; w0 *= inv; w1 *= inv;
            }
            float t = w0 * vv[lane] + w1 * vv[lane + 32]; RADD(t);
            if (lane == 0) f2[e] = t;
            if (layer == 0) {
                t = w0 * dxa[lane] + w1 * dxa[lane + 32]; RADD(t); if (lane == 0) dea[e] = t;
                t = w0 * dxb[lane] + w1 * dxb[lane + 32]; RADD(t); if (lane == 0) deb[e] = t;
                t = w0 * dxc[lane] + w1 * dxc[lane + 32]; RADD(t); if (lane == 0) dec[e] = t;
            }
            st1(sm, SM_ATT1 + e * 144 + lane * 2, 18432, w0);
            st1(sm, SM_ATT1 + e * 144 + (lane + 32) * 2, 18432, w1);
        }
        __syncthreads();

        // ---- attN[j][e] softmax (no max-sub) + x1 channel updates (layer0) ----
        for (int j = warp; j < 64; j += 32) {
            unsigned long long m0 = nmask[2 * j], m1 = nmask[2 * j + 1];
            float ss = s2v[j];
            float w[4];
            if ((m0 | m1) == 0ull) { w[0] = w[1] = w[2] = w[3] = 1.f / 128.f; }
            else {
                bool bt[4] = { (bool)((m0 >> lane) & 1ull), (bool)((m0 >> (lane + 32)) & 1ull),
                               (bool)((m1 >> lane) & 1ull), (bool)((m1 >> (lane + 32)) & 1ull) };
                float s = 0.f;
                #pragma unroll
                for (int t = 0; t < 4; t++) {
                    float v = ss + f2[lane + 32 * t];
                    v = v > 0.f ? v : ALPHA * v;
                    w[t] = bt[t] ? __expf(v) : 0.f;
                    s += w[t];
                }
                RADD(s);
                float inv = 1.f / s;
                #pragma unroll
                for (int t = 0; t < 4; t++) w[t] *= inv;
            }
            if (layer == 0) {
                float ta = w[0]*dea[lane] + w[1]*dea[lane+32] + w[2]*dea[lane+64] + w[3]*dea[lane+96];
                float tb = w[0]*deb[lane] + w[1]*deb[lane+32] + w[2]*deb[lane+64] + w[3]*deb[lane+96];
                float tc = w[0]*dec[lane] + w[1]*dec[lane+32] + w[2]*dec[lane+64] + w[3]*dec[lane+96];
                RADD(ta); RADD(tb); RADD(tc);
                if (lane == 0) {
                    float x1a = g_c1[1] + ta + dxa[j];
                    e1v[j] = x1a > 0.f ? x1a : ALPHA * x1a;
                    s2v[j] = tb + dxb[j];
                    vv[j]  = tc + dxc[j];
                }
            }
            #pragma unroll
            for (int t = 0; t < 4; t++)
                st1(sm, SM_ATTN + j * 272 + (lane + 32 * t) * 2, 17408, w[t]);
        }
        __syncthreads();

        // ---- P = attN @ att1 : M64 K128 N64 ----
        {
            int mt = warp >> 3, nt = warp & 7;
            float d[4] = {0.f, 0.f, 0.f, 0.f};
            uint32_t aHi = sbase + SM_ATTN + (mt * 16 + (lane & 15)) * 272 + (lane >> 4) * 16;
            uint32_t bHi = sbase + SM_ATT1 + (lane & 15) * 144 + nt * 16;
            #pragma unroll
            for (int k = 0; k < 8; k++) {
                uint32_t ah[4], al[4], bh[2], bl[2];
                ldm_x4(ah, aHi + k * 32);
                ldm_x4(al, aHi + 17408 + k * 32);
                ldm_x2t(bh, bHi + k * 2304);
                ldm_x2t(bl, bHi + 18432 + k * 2304);
                mma16816(d, ah, bh);
                mma16816(d, ah, bl);
                mma16816(d, al, bh);
            }
            int r = mt * 16 + (lane >> 2), c = nt * 8 + (lane & 3) * 2;
            st2(sm, SM_P + r * 144 + c * 2, 9216, d[0], d[1]);
            st2(sm, SM_P + (r + 8) * 144 + c * 2, 9216, d[2], d[3]);
        }
        __syncthreads();

        if (layer == 0) {
            // ---- node0 = P @ x0 ; +resid -> x1 (into SM_X) ----
            int mt = warp >> 3, nc = warp & 7;
            float d[8] = {0.f, 0.f, 0.f, 0.f, 0.f, 0.f, 0.f, 0.f};
            uint32_t aHi = sbase + SM_P + (mt * 16 + (lane & 15)) * 144 + (lane >> 4) * 16;
            uint32_t bHi = sbase + SM_X + (lane & 15) * 272 + nc * 32 + (lane >> 4) * 16;
            #pragma unroll
            for (int k = 0; k < 4; k++) {
                uint32_t ah[4], al[4], bh[4], bl[4];
                ldm_x4(ah, aHi + k * 32);
                ldm_x4(al, aHi + 9216 + k * 32);
                ldm_x4t(bh, bHi + k * 4352);
                ldm_x4t(bl, bHi + 17408 + k * 4352);
                mma16816(d, ah, bh); mma16816(d, ah, bl); mma16816(d, al, bh);
                mma16816(d + 4, ah, bh + 2); mma16816(d + 4, ah, bl + 2); mma16816(d + 4, al, bh + 2);
            }
            __syncthreads();
            int r = mt * 16 + (lane >> 2);
            #pragma unroll
            for (int t = 0; t < 2; t++) {
                int c = nc * 16 + t * 8 + (lane & 3) * 2;
                float v00 = d[t*4+0] + resid[r * 128 + c];
                float v01 = d[t*4+1] + resid[r * 128 + c + 1];
                float v10 = d[t*4+2] + resid[(r + 8) * 128 + c];
                float v11 = d[t*4+3] + resid[(r + 8) * 128 + c + 1];
                st2(sm, SM_X + r * 272 + c * 2, 17408, v00, v01);
                st2(sm, SM_X + (r + 8) * 272 + c * 2, 17408, v10, v11);
            }
            __syncthreads();
        } else {
            // ---- FUSED: copy g2w image -> base 0, AND y = P1 @ x1 -> SM_Y ----
            {
                const float4* src = (const float4*)g_w2img;
                float4* dst = (float4*)(sm + SM_G2W);
                for (int i = tid; i < 4352; i += 1024) dst[i] = src[i];
            }
            {
                int mt = warp >> 3, nc = warp & 7;
                float d[8] = {0.f, 0.f, 0.f, 0.f, 0.f, 0.f, 0.f, 0.f};
                uint32_t aHi = sbase + SM_P + (mt * 16 + (lane & 15)) * 144 + (lane >> 4) * 16;
                uint32_t bHi = sbase + SM_X + (lane & 15) * 272 + nc * 32 + (lane >> 4) * 16;
                #pragma unroll
                for (int k = 0; k < 4; k++) {
                    uint32_t ah[4], al[4], bh[4], bl[4];
                    ldm_x4(ah, aHi + k * 32);
                    ldm_x4(al, aHi + 9216 + k * 32);
                    ldm_x4t(bh, bHi + k * 4352);
                    ldm_x4t(bl, bHi + 17408 + k * 4352);
                    mma16816(d, ah, bh); mma16816(d, ah, bl); mma16816(d, al, bh);
                    mma16816(d + 4, ah, bh + 2); mma16816(d + 4, ah, bl + 2); mma16816(d + 4, al, bh + 2);
                }
                int r = mt * 16 + (lane >> 2);
                #pragma unroll
                for (int t = 0; t < 2; t++) {
                    int c = nc * 16 + t * 8 + (lane & 3) * 2;
                    st2(sm, SM_Y + r * 272 + c * 2, 17408, d[t*4+0], d[t*4+1]);
                    st2(sm, SM_Y + (r + 8) * 272 + c * 2, 17408, d[t*4+2], d[t*4+3]);
                }
            }
            __syncthreads();
            // ---- node1 = y @ g2w ; +resid -> resid (fp32) ----
            {
                int mt = warp >> 3, nc = warp & 7;
                float d[8] = {0.f, 0.f, 0.f, 0.f, 0.f, 0.f, 0.f, 0.f};
                uint32_t aHi = sbase + SM_Y + (mt * 16 + (lane & 15)) * 272 + (lane >> 4) * 16;
                uint32_t bHi = sbase + SM_G2W + (lane & 15) * 272 + nc * 32 + (lane >> 4) * 16;
                #pragma unroll
                for (int k = 0; k < 8; k++) {
                    uint32_t ah[4], al[4], bh[4], bl[4];
                    ldm_x4(ah, aHi + k * 32);
                    ldm_x4(al, aHi + 17408 + k * 32);
                    ldm_x4t(bh, bHi + k * 4352);
                    ldm_x4t(bl, bHi + 34816 + k * 4352);
                    mma16816(d, ah, bh); mma16816(d, ah, bl); mma16816(d, al, bh);
                    mma16816(d + 4, ah, bh + 2); mma16816(d + 4, ah, bl + 2); mma16816(d + 4, al, bh + 2);
                }
                int r = mt * 16 + (lane >> 2);
                #pragma unroll
                for (int t = 0; t < 2; t++) {
                    int c = nc * 16 + t * 8 + (lane & 3) * 2;
                    resid[r * 128 + c]           += d[t*4+0];
                    resid[r * 128 + c + 1]       += d[t*4+1];
                    resid[(r + 8) * 128 + c]     += d[t*4+2];
                    resid[(r + 8) * 128 + c + 1] += d[t*4+3];
                }
            }
            __syncthreads();
        }
    }

    // ---- Output: (x, x) from resid ----
    for (int j = warp; j < 64; j += 32) {
        float4 v = ((const float4*)resid)[j * 32 + lane];
        ((float4*)(out + ((size_t)b * 64 + j) * 128))[lane] = v;
        ((float4*)(out + BLD + ((size_t)b * 64 + j) * 128))[lane] = v;
    }
}

extern "C" void kernel_launch(void* const* d_in, const int* in_sizes, int n_in,
                              void* d_out, int out_size)
{
    const int*   inputs = (const int*)d_in[0];
    const float* HT     = (const float*)d_in[1];
    const float* emb    = (const float*)d_in[4];
    const float* emb2   = (const float*)d_in[5];
    const float* g1_w2  = (const float*)d_in[6];
    const float* g1_w3  = (const float*)d_in[7];
    const float* g1_q   = (const float*)d_in[8];
    const float* g1_a   = (const float*)d_in[9];
    const float* g1_a2  = (const float*)d_in[10];
    const float* g2_w   = (const float*)d_in[11];
    const float* g2_w2  = (const float*)d_in[12];
    const float* g2_w3  = (const float*)d_in[13];
    const float* g2_q   = (const float*)d_in[14];
    const float* g2_a   = (const float*)d_in[15];
    const float* g2_a2  = (const float*)d_in[16];
    float* out = (float*)d_out;

    cudaFuncSetAttribute(session_kernel,
                         cudaFuncAttributeMaxDynamicSharedMemorySize, SMEM_BYTES);

    precompute_kernel<<<dim3(2, 128), 128>>>(g1_w2, g1_w3, g1_q, g1_a, g1_a2,
                                             g2_w2, g2_w3, g2_q, g2_a, g2_a2);
    img_kernel<<<64, 256>>>(g2_w);
    session_kernel<<<Bb, 1024, SMEM_BYTES>>>(inputs, HT, emb, emb2, out);
}

// round 9
// speedup vs baseline: 2.2674x; 1.0501x over previous
#include <cuda_runtime.h>
#include <cuda_bf16.h>
#include <cstdint>

#define FULL 0xFFFFFFFFu
constexpr int Bb = 512;
constexpr float ALPHA = 0.2f;

// ---------------- mma / ldmatrix helpers (baseline PTX, sm_80+) ----------------
__device__ __forceinline__ void mma16816(float* d, const uint32_t* a, const uint32_t* b) {
    asm volatile("mma.sync.aligned.m16n8k16.row.col.f32.bf16.bf16.f32 "
        "{%0,%1,%2,%3}, {%4,%5,%6,%7}, {%8,%9}, {%0,%1,%2,%3};"
        : "+f"(d[0]), "+f"(d[1]), "+f"(d[2]), "+f"(d[3])
        : "r"(a[0]), "r"(a[1]), "r"(a[2]), "r"(a[3]), "r"(b[0]), "r"(b[1]));
}
__device__ __forceinline__ void ldm_x4(uint32_t* r, uint32_t addr) {
    asm volatile("ldmatrix.sync.aligned.m8n8.x4.shared.b16 {%0,%1,%2,%3}, [%4];"
        : "=r"(r[0]), "=r"(r[1]), "=r"(r[2]), "=r"(r[3]) : "r"(addr));
}
__device__ __forceinline__ void ldm_x4t(uint32_t* r, uint32_t addr) {
    asm volatile("ldmatrix.sync.aligned.m8n8.x4.trans.shared.b16 {%0,%1,%2,%3}, [%4];"
        : "=r"(r[0]), "=r"(r[1]), "=r"(r[2]), "=r"(r[3]) : "r"(addr));
}
__device__ __forceinline__ void ldm_x2t(uint32_t* r, uint32_t addr) {
    asm volatile("ldmatrix.sync.aligned.m8n8.x2.trans.shared.b16 {%0,%1}, [%2];"
        : "=r"(r[0]), "=r"(r[1]) : "r"(addr));
}
__device__ __forceinline__ uint32_t smem_u32(const void* p) {
    uint32_t a;
    asm("{ .reg .u64 t; cvta.to.shared.u64 t, %1; cvt.u32.u64 %0, t; }" : "=r"(a) : "l"(p));
    return a;
}

#define RADD(v) { _Pragma("unroll") for (int _o = 16; _o; _o >>= 1) v += __shfl_xor_sync(FULL, v, _o); }

// ---------------- precomputed globals ----------------
// g_u: 0=u1a 1=u2a 2=u3a 3=u1b 4=u2b 5=u3g(=g2w@u3b)
__device__ float g_u[6][128];
__device__ float g_u3b[128];
__device__ float g_c1[2];
// g2w as bf16 hi[128][136] | lo[128][136] (row=k, col=d), 69632 bytes
__device__ __align__(16) uint8_t g_w2img[69632];

// grid (2, 128) x 128 threads
__global__ void precompute_kernel(
    const float* __restrict__ w2a, const float* __restrict__ w3a,
    const float* __restrict__ qa,  const float* __restrict__ aa,
    const float* __restrict__ a2a,
    const float* __restrict__ w2b, const float* __restrict__ w3b,
    const float* __restrict__ qb,  const float* __restrict__ ab,
    const float* __restrict__ a2b)
{
    const int layer = blockIdx.x;
    const int k     = blockIdx.y;
    const int c     = threadIdx.x;
    const int wp    = c >> 5, ln = c & 31;
    const float* w2 = layer ? w2b : w2a;
    const float* w3 = layer ? w3b : w3a;
    const float* q  = layer ? qb  : qa;
    const float* a  = layer ? ab  : aa;
    const float* a2 = layer ? a2b : a2a;

    float w2v = w2[k * 128 + c];
    float p1 = w2v * a[128 + c];
    float p2 = w2v * a2[c];
    float p3 = w3[k * 128 + c] * a2[128 + c];
    float p4 = (k == 0) ? q[c] * a[c] : 0.f;
    RADD(p1); RADD(p2); RADD(p3); RADD(p4);
    __shared__ float sh[4][4];
    if (ln == 0) { sh[0][wp] = p1; sh[1][wp] = p2; sh[2][wp] = p3; sh[3][wp] = p4; }
    __syncthreads();
    if (c == 0) {
        float u1 = sh[0][0] + sh[0][1] + sh[0][2] + sh[0][3];
        float u2 = sh[1][0] + sh[1][1] + sh[1][2] + sh[1][3];
        float u3 = sh[2][0] + sh[2][1] + sh[2][2] + sh[2][3];
        if (layer == 0) { g_u[0][k] = u1; g_u[1][k] = u2; g_u[2][k] = u3; }
        else            { g_u[3][k] = u1; g_u[4][k] = u2; g_u3b[k] = u3; }
        if (k == 0) g_c1[layer] = sh[3][0] + sh[3][1] + sh[3][2] + sh[3][3];
    }
}

// 64 blocks x 256 threads
__global__ void img_kernel(const float* __restrict__ g2w) {
    int idx = blockIdx.x * 256 + threadIdx.x;
    int kk = idx >> 7, d = idx & 127;
    float v = g2w[kk * 128 + d];
    __nv_bfloat16 h = __float2bfloat16(v);
    *(__nv_bfloat16*)(g_w2img + (kk * 136 + d) * 2) = h;
    *(__nv_bfloat16*)(g_w2img + 34816 + (kk * 136 + d) * 2) =
        __float2bfloat16(v - __bfloat162float(h));
    int gw = blockIdx.x * 8 + (threadIdx.x >> 5);
    if (gw < 128) {
        int ln = threadIdx.x & 31;
        float s = 0.f;
        #pragma unroll
        for (int t = 0; t < 4; t++)
            s += g2w[gw * 128 + ln + 32 * t] * g_u3b[ln + 32 * t];
        RADD(s);
        if (ln == 0) g_u[5][gw] = s;
    }
}

// ---------------- smem layout (bytes) ----------------
constexpr int SM_ATT1  = 0;        // hi [128][72] | lo +18432 ; 36864
constexpr int SM_ATTN  = 36864;    // hi [64][136] | lo +17408 ; 34816
constexpr int SM_G2W   = 0;        // 69632 (overlaps ATT1+ATTN; layer1 after P1)
constexpr int SM_X     = 71680;    // hi [64][136] | lo ; 34816
constexpr int SM_Y     = 106496;   // hi [64][136] | lo ; 34816
constexpr int SM_P     = 141312;   // hi [64][72] | lo ; 18432
constexpr int SM_RESID = 159744;   // fp32 [64][128] 32768
constexpr int SM_E1V   = 192512;
constexpr int SM_S2    = 192768;
constexpr int SM_VV    = 193024;
constexpr int SM_DXA   = 193280;
constexpr int SM_DXB   = 193536;
constexpr int SM_DXC   = 193792;
constexpr int SM_F2    = 194048;
constexpr int SM_DEA   = 194560;
constexpr int SM_DEB   = 195072;
constexpr int SM_DEC   = 195584;
constexpr int SM_EMASK = 196096;   // 128 u64
constexpr int SM_NMASK = 197120;   // 64 x 2 u64
constexpr int SMEM_BYTES = 198144;

__device__ __forceinline__ void st2(uint8_t* sm, int off, int loB, float a, float b) {
    __nv_bfloat16 h0 = __float2bfloat16(a), h1 = __float2bfloat16(b);
    *(__nv_bfloat162*)(sm + off) = __halves2bfloat162(h0, h1);
    *(__nv_bfloat162*)(sm + off + loB) = __floats2bfloat162_rn(
        a - __bfloat162float(h0), b - __bfloat162float(h1));
}
__device__ __forceinline__ void st1(uint8_t* sm, int off, int loB, float a) {
    __nv_bfloat16 h = __float2bfloat16(a);
    *(__nv_bfloat16*)(sm + off) = h;
    *(__nv_bfloat16*)(sm + off + loB) = __float2bfloat16(a - __bfloat162float(h));
}

__global__ __launch_bounds__(1024, 1) void session_kernel(
    const int*   __restrict__ inputs,
    const float* __restrict__ HT,
    const float* __restrict__ emb,
    const float* __restrict__ emb2,
    float*       __restrict__ out)
{
    extern __shared__ __align__(16) uint8_t sm[];
    const int tid  = threadIdx.x;
    const int warp = tid >> 5;
    const int lane = tid & 31;
    const int b    = blockIdx.x;
    const size_t BLD = (size_t)Bb * 64 * 128;
    uint32_t sbase = smem_u32(sm);

    float* e1v = (float*)(sm + SM_E1V);
    float* s2v = (float*)(sm + SM_S2);
    float* vv  = (float*)(sm + SM_VV);
    float* dxa = (float*)(sm + SM_DXA);
    float* dxb = (float*)(sm + SM_DXB);
    float* dxc = (float*)(sm + SM_DXC);
    float* f2  = (float*)(sm + SM_F2);
    float* dea = (float*)(sm + SM_DEA);
    float* deb = (float*)(sm + SM_DEB);
    float* dec = (float*)(sm + SM_DEC);
    unsigned long long* emask = (unsigned long long*)(sm + SM_EMASK);
    unsigned long long* nmask = (unsigned long long*)(sm + SM_NMASK);
    float* resid = (float*)(sm + SM_RESID);

    // ---- Phase 0: gathers, x0 hi/lo image, 6-channel dots, masks ----
    for (int j = warp; j < 64; j += 32) {
        int tok = inputs[b * 64 + j];
        float4 v = ((const float4*)(emb + (size_t)tok * 128))[lane];
        ((float4*)resid)[j * 32 + lane] = v;
        float4 v2 = ((const float4*)(emb2 + (size_t)tok * 128))[lane];
        ((float4*)(out + 2 * BLD + ((size_t)b * 64 + j) * 128))[lane] = v2;
        st2(sm, SM_X + j * 272 + 8 * lane, 17408, v.x, v.y);
        st2(sm, SM_X + j * 272 + 8 * lane + 4, 17408, v.z, v.w);
        float p[6];
        #pragma unroll
        for (int c = 0; c < 6; c++) {
            float4 gu = ((const float4*)g_u[c])[lane];
            p[c] = v.x * gu.x + v.y * gu.y + v.z * gu.z + v.w * gu.w;
        }
        #pragma unroll
        for (int c = 0; c < 6; c++) RADD(p[c]);
        if (lane == 0) {
            float e = g_c1[0] + p[0];
            e1v[j] = e > 0.f ? e : ALPHA * e;
            s2v[j] = p[1]; vv[j] = p[2];
            dxa[j] = p[3]; dxb[j] = p[4]; dxc[j] = p[5];
        }
    }
    for (int e = warp; e < 128; e += 32) {
        const float* row = HT + ((size_t)b * 128 + e) * 64;
        unsigned lo = __ballot_sync(FULL, row[lane] > 0.f);
        unsigned hi = __ballot_sync(FULL, row[lane + 32] > 0.f);
        if (lane == 0) emask[e] = (unsigned long long)lo | ((unsigned long long)hi << 32);
    }
    __syncthreads();
    // nmask via ballot-transpose
    {
        unsigned long long eA = emask[lane],      eB = emask[lane + 32];
        unsigned long long eC = emask[lane + 64], eD = emask[lane + 96];
        #pragma unroll
        for (int t = 0; t < 2; t++) {
            int j = warp + 32 * t;
            unsigned b0 = __ballot_sync(FULL, (eA >> j) & 1ull);
            unsigned b1 = __ballot_sync(FULL, (eB >> j) & 1ull);
            unsigned b2 = __ballot_sync(FULL, (eC >> j) & 1ull);
            unsigned b3 = __ballot_sync(FULL, (eD >> j) & 1ull);
            if (lane == 0) {
                nmask[2 * j]     = (unsigned long long)b0 | ((unsigned long long)b1 << 32);
                nmask[2 * j + 1] = (unsigned long long)b2 | ((unsigned long long)b3 << 32);
            }
        }
    }
    __syncthreads();

    for (int layer = 0; layer < 2; layer++) {
        // ---- att1[e][j] softmax: 2 hoisted exps/warp, unnormalized channels ----
        {
            float ex0 = __expf(e1v[lane]), ex32 = __expf(e1v[lane + 32]);
            float vv0 = vv[lane], vv32 = vv[lane + 32];
            float da0 = 0.f, da32 = 0.f, db0 = 0.f, db32 = 0.f, dc0 = 0.f, dc32 = 0.f;
            if (layer == 0) {
                da0 = dxa[lane]; da32 = dxa[lane + 32];
                db0 = dxb[lane]; db32 = dxb[lane + 32];
                dc0 = dxc[lane]; dc32 = dxc[lane + 32];
            }
            for (int e = warp; e < 128; e += 32) {
                unsigned long long m = emask[e];
                bool b0 = (m >> lane) & 1ull, b1 = (m >> (lane + 32)) & 1ull;
                float w0 = (m == 0ull) ? (1.f / 64.f) : (b0 ? ex0 : 0.f);
                float w1 = (m == 0ull) ? (1.f / 64.f) : (b1 ? ex32 : 0.f);
                float s = w0 + w1;
                float t = w0 * vv0 + w1 * vv32;
                float ta = 0.f, tb = 0.f, tc = 0.f;
                if (layer == 0) {
                    ta = w0 * da0 + w1 * da32;
                    tb = w0 * db0 + w1 * db32;
                    tc = w0 * dc0 + w1 * dc32;
                }
                RADD(s); RADD(t);
                if (layer == 0) { RADD(ta); RADD(tb); RADD(tc); }
                float inv = 1.f / s;
                w0 *= inv; w1 *= inv;
                if (lane == 0) {
                    f2[e] = t * inv;
                    if (layer == 0) { dea[e] = ta * inv; deb[e] = tb * inv; dec[e] = tc * inv; }
                }
                st1(sm, SM_ATT1 + e * 144 + lane * 2, 18432, w0);
                st1(sm, SM_ATT1 + e * 144 + (lane + 32) * 2, 18432, w1);
            }
        }
        __syncthreads();

        // ---- attN[j][e] softmax via factored exp: hoisted ef/ef02 per lane ----
        {
            float f2l[4], efv[4], ef02v[4];
            float dav[4], dbv[4], dcv[4];
            #pragma unroll
            for (int t = 0; t < 4; t++) {
                float f = f2[lane + 32 * t];
                f2l[t] = f;
                efv[t] = __expf(f);
                ef02v[t] = __expf(ALPHA * f);
            }
            if (layer == 0) {
                #pragma unroll
                for (int t = 0; t < 4; t++) {
                    dav[t] = dea[lane + 32 * t];
                    dbv[t] = deb[lane + 32 * t];
                    dcv[t] = dec[lane + 32 * t];
                }
            }
            for (int j = warp; j < 64; j += 32) {
                unsigned long long m0 = nmask[2 * j], m1 = nmask[2 * j + 1];
                float ss = s2v[j];
                float esj = __expf(ss), es02j = __expf(ALPHA * ss);
                bool empty = (m0 | m1) == 0ull;
                bool bt[4] = { (bool)((m0 >> lane) & 1ull), (bool)((m0 >> (lane + 32)) & 1ull),
                               (bool)((m1 >> lane) & 1ull), (bool)((m1 >> (lane + 32)) & 1ull) };
                float w[4];
                float s = 0.f;
                #pragma unroll
                for (int t = 0; t < 4; t++) {
                    float val = (ss + f2l[t] > 0.f) ? esj * efv[t] : es02j * ef02v[t];
                    w[t] = empty ? (1.f / 128.f) : (bt[t] ? val : 0.f);
                    s += w[t];
                }
                float ta = 0.f, tb = 0.f, tc = 0.f;
                if (layer == 0) {
                    #pragma unroll
                    for (int t = 0; t < 4; t++) {
                        ta += w[t] * dav[t];
                        tb += w[t] * dbv[t];
                        tc += w[t] * dcv[t];
                    }
                }
                RADD(s);
                if (layer == 0) { RADD(ta); RADD(tb); RADD(tc); }
                float inv = 1.f / s;
                #pragma unroll
                for (int t = 0; t < 4; t++) w[t] *= inv;
                if (layer == 0 && lane == 0) {
                    float x1a = g_c1[1] + ta * inv + dxa[j];
                    e1v[j] = x1a > 0.f ? x1a : ALPHA * x1a;
                    s2v[j] = tb * inv + dxb[j];
                    vv[j]  = tc * inv + dxc[j];
                }
                #pragma unroll
                for (int t = 0; t < 4; t++)
                    st1(sm, SM_ATTN + j * 272 + (lane + 32 * t) * 2, 17408, w[t]);
            }
        }
        __syncthreads();

        // ---- P = attN @ att1 : M64 K128 N64 ----
        {
            int mt = warp >> 3, nt = warp & 7;
            float d[4] = {0.f, 0.f, 0.f, 0.f};
            uint32_t aHi = sbase + SM_ATTN + (mt * 16 + (lane & 15)) * 272 + (lane >> 4) * 16;
            uint32_t bHi = sbase + SM_ATT1 + (lane & 15) * 144 + nt * 16;
            #pragma unroll
            for (int k = 0; k < 8; k++) {
                uint32_t ah[4], al[4], bh[2], bl[2];
                ldm_x4(ah, aHi + k * 32);
                ldm_x4(al, aHi + 17408 + k * 32);
                ldm_x2t(bh, bHi + k * 2304);
                ldm_x2t(bl, bHi + 18432 + k * 2304);
                mma16816(d, ah, bh);
                mma16816(d, ah, bl);
                mma16816(d, al, bh);
            }
            int r = mt * 16 + (lane >> 2), c = nt * 8 + (lane & 3) * 2;
            st2(sm, SM_P + r * 144 + c * 2, 9216, d[0], d[1]);
            st2(sm, SM_P + (r + 8) * 144 + c * 2, 9216, d[2], d[3]);
        }
        __syncthreads();

        if (layer == 0) {
            // ---- node0 = P @ x0 ; +resid -> x1 (into SM_X) ----
            int mt = warp >> 3, nc = warp & 7;
            float d[8] = {0.f, 0.f, 0.f, 0.f, 0.f, 0.f, 0.f, 0.f};
            uint32_t aHi = sbase + SM_P + (mt * 16 + (lane & 15)) * 144 + (lane >> 4) * 16;
            uint32_t bHi = sbase + SM_X + (lane & 15) * 272 + nc * 32 + (lane >> 4) * 16;
            #pragma unroll
            for (int k = 0; k < 4; k++) {
                uint32_t ah[4], al[4], bh[4], bl[4];
                ldm_x4(ah, aHi + k * 32);
                ldm_x4(al, aHi + 9216 + k * 32);
                ldm_x4t(bh, bHi + k * 4352);
                ldm_x4t(bl, bHi + 17408 + k * 4352);
                mma16816(d, ah, bh); mma16816(d, ah, bl); mma16816(d, al, bh);
                mma16816(d + 4, ah, bh + 2); mma16816(d + 4, ah, bl + 2); mma16816(d + 4, al, bh + 2);
            }
            __syncthreads();
            int r = mt * 16 + (lane >> 2);
            #pragma unroll
            for (int t = 0; t < 2; t++) {
                int c = nc * 16 + t * 8 + (lane & 3) * 2;
                float v00 = d[t*4+0] + resid[r * 128 + c];
                float v01 = d[t*4+1] + resid[r * 128 + c + 1];
                float v10 = d[t*4+2] + resid[(r + 8) * 128 + c];
                float v11 = d[t*4+3] + resid[(r + 8) * 128 + c + 1];
                st2(sm, SM_X + r * 272 + c * 2, 17408, v00, v01);
                st2(sm, SM_X + (r + 8) * 272 + c * 2, 17408, v10, v11);
            }
            __syncthreads();
        } else {
            // ---- FUSED: copy g2w image -> base 0, AND y = P1 @ x1 -> SM_Y ----
            {
                const float4* src = (const float4*)g_w2img;
                float4* dst = (float4*)(sm + SM_G2W);
                for (int i = tid; i < 4352; i += 1024) dst[i] = src[i];
            }
            {
                int mt = warp >> 3, nc = warp & 7;
                float d[8] = {0.f, 0.f, 0.f, 0.f, 0.f, 0.f, 0.f, 0.f};
                uint32_t aHi = sbase + SM_P + (mt * 16 + (lane & 15)) * 144 + (lane >> 4) * 16;
                uint32_t bHi = sbase + SM_X + (lane & 15) * 272 + nc * 32 + (lane >> 4) * 16;
                #pragma unroll
                for (int k = 0; k < 4; k++) {
                    uint32_t ah[4], al[4], bh[4], bl[4];
                    ldm_x4(ah, aHi + k * 32);
                    ldm_x4(al, aHi + 9216 + k * 32);
                    ldm_x4t(bh, bHi + k * 4352);
                    ldm_x4t(bl, bHi + 17408 + k * 4352);
                    mma16816(d, ah, bh); mma16816(d, ah, bl); mma16816(d, al, bh);
                    mma16816(d + 4, ah, bh + 2); mma16816(d + 4, ah, bl + 2); mma16816(d + 4, al, bh + 2);
                }
                int r = mt * 16 + (lane >> 2);
                #pragma unroll
                for (int t = 0; t < 2; t++) {
                    int c = nc * 16 + t * 8 + (lane & 3) * 2;
                    st2(sm, SM_Y + r * 272 + c * 2, 17408, d[t*4+0], d[t*4+1]);
                    st2(sm, SM_Y + (r + 8) * 272 + c * 2, 17408, d[t*4+2], d[t*4+3]);
                }
            }
            __syncthreads();
            // ---- node1 = y @ g2w ; +resid -> resid (fp32) ----
            {
                int mt = warp >> 3, nc = warp & 7;
                float d[8] = {0.f, 0.f, 0.f, 0.f, 0.f, 0.f, 0.f, 0.f};
                uint32_t aHi = sbase + SM_Y + (mt * 16 + (lane & 15)) * 272 + (lane >> 4) * 16;
                uint32_t bHi = sbase + SM_G2W + (lane & 15) * 272 + nc * 32 + (lane >> 4) * 16;
                #pragma unroll
                for (int k = 0; k < 8; k++) {
                    uint32_t ah[4], al[4], bh[4], bl[4];
                    ldm_x4(ah, aHi + k * 32);
                    ldm_x4(al, aHi + 17408 + k * 32);
                    ldm_x4t(bh, bHi + k * 4352);
                    ldm_x4t(bl, bHi + 34816 + k * 4352);
                    mma16816(d, ah, bh); mma16816(d, ah, bl); mma16816(d, al, bh);
                    mma16816(d + 4, ah, bh + 2); mma16816(d + 4, ah, bl + 2); mma16816(d + 4, al, bh + 2);
                }
                int r = mt * 16 + (lane >> 2);
                #pragma unroll
                for (int t = 0; t < 2; t++) {
                    int c = nc * 16 + t * 8 + (lane & 3) * 2;
                    resid[r * 128 + c]           += d[t*4+0];
                    resid[r * 128 + c + 1]       += d[t*4+1];
                    resid[(r + 8) * 128 + c]     += d[t*4+2];
                    resid[(r + 8) * 128 + c + 1] += d[t*4+3];
                }
            }
            __syncthreads();
        }
    }

    // ---- Output: (x, x) from resid ----
    for (int j = warp; j < 64; j += 32) {
        float4 v = ((const float4*)resid)[j * 32 + lane];
        ((float4*)(out + ((size_t)b * 64 + j) * 128))[lane] = v;
        ((float4*)(out + BLD + ((size_t)b * 64 + j) * 128))[lane] = v;
    }
}

extern "C" void kernel_launch(void* const* d_in, const int* in_sizes, int n_in,
                              void* d_out, int out_size)
{
    const int*   inputs = (const int*)d_in[0];
    const float* HT     = (const float*)d_in[1];
    const float* emb    = (const float*)d_in[4];
    const float* emb2   = (const float*)d_in[5];
    const float* g1_w2  = (const float*)d_in[6];
    const float* g1_w3  = (const float*)d_in[7];
    const float* g1_q   = (const float*)d_in[8];
    const float* g1_a   = (const float*)d_in[9];
    const float* g1_a2  = (const float*)d_in[10];
    const float* g2_w   = (const float*)d_in[11];
    const float* g2_w2  = (const float*)d_in[12];
    const float* g2_w3  = (const float*)d_in[13];
    const float* g2_q   = (const float*)d_in[14];
    const float* g2_a   = (const float*)d_in[15];
    const float* g2_a2  = (const float*)d_in[16];
    float* out = (float*)d_out;

    cudaFuncSetAttribute(session_kernel,
                         cudaFuncAttributeMaxDynamicSharedMemorySize, SMEM_BYTES);

    precompute_kernel<<<dim3(2, 128), 128>>>(g1_w2, g1_w3, g1_q, g1_a, g1_a2,
                                             g2_w2, g2_w3, g2_q, g2_a, g2_a2);
    img_kernel<<<64, 256>>>(g2_w);
    session_kernel<<<Bb, 1024, SMEM_BYTES>>>(inputs, HT, emb, emb2, out);
}